// round 14
// baseline (speedup 1.0000x reference)
#include <cuda_runtime.h>
#include <cuda_fp16.h>

#define DD 128
#define NN 25600
#define EE 409600
#define BB 128
#define EFE 1024
#define LL 8
#define KK 32
#define NPG 200

// ---------------- scratch (device globals; allocation-free rule) ----------------
__device__ __align__(256) unsigned g_eph0[EE * 64];
__device__ __align__(256) unsigned g_eph1[EE * 64];
__device__ __align__(256) unsigned g_hph0[NN * 64];
__device__ __align__(256) unsigned g_hpl0[NN * 64];
__device__ __align__(256) unsigned g_hph1[NN * 64];
__device__ __align__(256) unsigned g_hpl1[NN * 64];
__device__ __align__(256) unsigned g_fni16[NN * 64];
__device__ __align__(256) unsigned g_fnj16[NN * 64];
__device__ __align__(256) float g_hs[NN * DD];
__device__ __align__(256) float g_hfin[NN * DD];
__device__ __align__(256) float g_hsort[NN * DD];
__device__ __align__(256) float g_score[EE];
__device__ __align__(256) float g_lastch[NN];
__device__ __align__(256) int   g_topk[BB * KK];
__device__ __align__(256) float g_ft[BB * DD];
__device__ __align__(256) float g_sl[BB];
__device__ __align__(256) float g_sr[BB];
__device__ __align__(256) float g_gv[BB * DD];
__device__ __align__(256) float g_embW[100 * DD];
__device__ __align__(256) int   g_cursor[NN];
__device__ __align__(256) int   g_rowstart[NN + 1];
__device__ __align__(256) int   g_perm[EE];
__device__ __align__(256) int   g_psrc[EE];
__device__ __align__(256) int   g_pdst[EE];
__device__ __align__(256) int   g_ptoke[EE];
__device__ __align__(256) unsigned g_wpkh[33 * 8192];
__device__ __align__(256) unsigned g_wpkl[33 * 8192];

// ---------------- helpers ----------------
__device__ __forceinline__ unsigned packsplit(float x0, float x1, unsigned& lo) {
    __half h0 = __float2half_rn(x0), h1 = __float2half_rn(x1);
    __half l0 = __float2half_rn(x0 - __half2float(h0));
    __half l1 = __float2half_rn(x1 - __half2float(h1));
    lo = ((unsigned)__half_as_ushort(l1) << 16) | (unsigned)__half_as_ushort(l0);
    return ((unsigned)__half_as_ushort(h1) << 16) | (unsigned)__half_as_ushort(h0);
}
__device__ __forceinline__ unsigned pack2(float x0, float x1) {
    __half2 h2 = __floats2half2_rn(x0, x1);
    return reinterpret_cast<unsigned&>(h2);
}
__device__ __forceinline__ float2 unpack2(unsigned u) {
    return __half22float2(reinterpret_cast<__half2&>(u));
}
__device__ __forceinline__ void mma16(float c[4], const unsigned a[4], const unsigned b[2]) {
    asm volatile(
        "mma.sync.aligned.m16n8k16.row.col.f32.f16.f16.f32 "
        "{%0,%1,%2,%3},{%4,%5,%6,%7},{%8,%9},{%0,%1,%2,%3};"
        : "+f"(c[0]), "+f"(c[1]), "+f"(c[2]), "+f"(c[3])
        : "r"(a[0]), "r"(a[1]), "r"(a[2]), "r"(a[3]), "r"(b[0]), "r"(b[1]));
}
__device__ __forceinline__ void ldsm4(unsigned r[4], unsigned addr) {
    asm volatile("ldmatrix.sync.aligned.m8n8.x4.shared.b16 {%0,%1,%2,%3}, [%4];"
        : "=r"(r[0]), "=r"(r[1]), "=r"(r[2]), "=r"(r[3]) : "r"(addr));
}
__device__ __forceinline__ void cpasync16(unsigned saddr, const void* g) {
    asm volatile("cp.async.ca.shared.global [%0], [%1], 16;" :: "r"(saddr), "l"(g));
}

// ---------------- CSR build + edge permutation ----------------
__global__ void k_zero_cursor() {
    int i = blockIdx.x * blockDim.x + threadIdx.x;
    if (i < NN) g_cursor[i] = 0;
}
__global__ void k_count(const int* __restrict__ dst) {
    int e = blockIdx.x * blockDim.x + threadIdx.x;
    if (e < EE) atomicAdd(&g_cursor[dst[e]], 1);
}
__global__ void k_scan() {
    __shared__ int s[1024];
    __shared__ int carry;
    int tid = threadIdx.x;
    if (tid == 0) carry = 0;
    __syncthreads();
    for (int base = 0; base < NN; base += 1024) {
        int i = base + tid;
        int v = (i < NN) ? g_cursor[i] : 0;
        s[tid] = v;
        __syncthreads();
        for (int off = 1; off < 1024; off <<= 1) {
            int t = (tid >= off) ? s[tid - off] : 0;
            __syncthreads();
            s[tid] += t;
            __syncthreads();
        }
        int excl = s[tid] - v;
        int bc = carry;
        if (i < NN) g_rowstart[i] = bc + excl;
        __syncthreads();
        if (tid == 0) carry = bc + s[1023];
        __syncthreads();
    }
    if (tid == 0) g_rowstart[NN] = carry;
}
__global__ void k_copy_cursor() {
    int i = blockIdx.x * blockDim.x + threadIdx.x;
    if (i < NN) g_cursor[i] = g_rowstart[i];
}
__global__ void k_scatter(const int* __restrict__ dst) {
    int e = blockIdx.x * blockDim.x + threadIdx.x;
    if (e < EE) {
        int p = atomicAdd(&g_cursor[dst[e]], 1);
        g_perm[p] = e;
    }
}
__global__ void k_permute(const int* __restrict__ src, const int* __restrict__ dst,
                          const int* __restrict__ toke) {
    int p = blockIdx.x * blockDim.x + threadIdx.x;
    if (p < EE) {
        int e = g_perm[p];
        g_psrc[p] = src[e];
        g_pdst[p] = dst[e];
        g_ptoke[p] = toke[e];
    }
}

// ---------------- init: h = relu(token_emb[tokens_h]) -> packed ----------------
__global__ void k_hinit(const int* __restrict__ tok, const float* __restrict__ emb) {
    int i = blockIdx.x * blockDim.x + threadIdx.x;
    if (i >= NN * 32) return;
    int n = i >> 5, c4 = i & 31;
    float4 v = ((const float4*)emb)[tok[n] * 32 + c4];
    v.x = fmaxf(v.x, 0.f); v.y = fmaxf(v.y, 0.f);
    v.z = fmaxf(v.z, 0.f); v.w = fmaxf(v.w, 0.f);
    unsigned lo0, lo1;
    unsigned hi0 = packsplit(v.x, v.y, lo0);
    unsigned hi1 = packsplit(v.z, v.w, lo1);
    ((uint2*)g_hph0)[n * 32 + c4] = make_uint2(hi0, hi1);
    ((uint2*)g_hpl0)[n * 32 + c4] = make_uint2(lo0, lo1);
}

__global__ void k_embw(const float* __restrict__ etok, const float* __restrict__ W) {
    int t = blockIdx.x, n = threadIdx.x;
    float acc = 0.f;
    #pragma unroll 8
    for (int k = 0; k < DD; k++) acc += etok[t * DD + k] * W[k * DD + n];
    g_embW[t * DD + n] = acc;
}

// ---------------- weight pre-pack ----------------
__global__ void k_wpack(const float* __restrict__ Wni, const float* __restrict__ Wnj,
                        const float* __restrict__ Wno, const float* __restrict__ Wfij,
                        const float* __restrict__ Wf) {
    extern __shared__ float sw[];
    int m = blockIdx.x, tid = threadIdx.x;
    const float* W = (m < 8) ? Wni + m * 16384
                   : (m < 16) ? Wnj + (m - 8) * 16384
                   : (m < 24) ? Wno + (m - 16) * 16384
                   : (m < 32) ? Wfij + (m - 24) * 16384
                   : Wf;
    for (int i = tid; i < 16384; i += 256) {
        int k = i >> 7, n = i & 127;
        sw[n * 129 + k] = W[i];
    }
    __syncthreads();
    int n = tid >> 1, ko = (tid & 1) * 64;
    #pragma unroll 8
    for (int p = 0; p < 32; p++) {
        int k = ko + 2 * p;
        float f0 = sw[n * 129 + k], f1 = sw[n * 129 + k + 1];
        unsigned lo;
        unsigned hi = packsplit(f0, f1, lo);
        g_wpkh[m * 8192 + n * 64 + (ko >> 1) + p] = hi;
        g_wpkl[m * 8192 + n * 64 + (ko >> 1) + p] = lo;
    }
}

// ================= split-fp16 tensor-core GEMM core =================
#define PADH 20
#define SMEM_T3 ((2 * 10240 + 128) * 4)
#define SMEM_T1 ((2 * 5120 + 128) * 4)

extern __shared__ unsigned smem_u[];

template <int TERMS>
__device__ __forceinline__ void mma_tile_t(const unsigned* __restrict__ AH,
                                           const unsigned* __restrict__ AL,
                                           const unsigned* __restrict__ WH,
                                           const unsigned* __restrict__ WL,
                                           int m0, float acc[2][8][4],
                                           int tid, int lane, int warp_m, int warp_n) {
    constexpr bool SPLITA = (TERMS == 3);
    constexpr bool WLO = (TERMS >= 2);
    constexpr unsigned OAL = 2560u;
    constexpr unsigned OWH = SPLITA ? 5120u : 2560u;
    constexpr unsigned OWL = OWH + 2560u;
    constexpr unsigned BUF = 2560u * (2 + (SPLITA ? 1 : 0) + (WLO ? 1 : 0));
    unsigned sb = (unsigned)__cvta_generic_to_shared(smem_u);
    int row_in = lane & 7, grp = lane >> 3;
    unsigned aHaddr[2], aLaddr[2];
    #pragma unroll
    for (int mf = 0; mf < 2; mf++) {
        int r = warp_m * 32 + mf * 16 + (grp & 1) * 8 + row_in;
        int p = (grp >> 1) * 4;
        aHaddr[mf] = sb + (r * PADH + p) * 4;
        if (SPLITA) aLaddr[mf] = sb + (OAL + r * PADH + p) * 4;
    }
    unsigned bHaddr[4], bLaddr[4];
    #pragma unroll
    for (int q = 0; q < 4; q++) {
        int n = warp_n * 64 + (2 * q + (grp >> 1)) * 8 + row_in;
        int p = (grp & 1) * 4;
        bHaddr[q] = sb + (OWH + n * PADH + p) * 4;
        if (WLO) bLaddr[q] = sb + (OWL + n * PADH + p) * 4;
    }
    int r0 = tid >> 2, c0 = tid & 3;
    int r1 = r0 + 64;

    #define COPY_CHUNK(kc, b) do {                                                   \
        unsigned base = sb + (b) * (BUF * 4);                                        \
        unsigned d0 = (r0 * PADH + c0 * 4) * 4, d1 = (r1 * PADH + c0 * 4) * 4;       \
        size_t ga0 = (size_t)(m0 + r0) * 64 + (kc) * 16 + c0 * 4;                    \
        size_t ga1 = (size_t)(m0 + r1) * 64 + (kc) * 16 + c0 * 4;                    \
        size_t gw0 = (size_t)r0 * 64 + (kc) * 16 + c0 * 4;                           \
        size_t gw1 = (size_t)r1 * 64 + (kc) * 16 + c0 * 4;                           \
        cpasync16(base + d0, AH + ga0);                                              \
        cpasync16(base + d1, AH + ga1);                                              \
        if (SPLITA) {                                                                \
            cpasync16(base + OAL * 4 + d0, AL + ga0);                                \
            cpasync16(base + OAL * 4 + d1, AL + ga1);                                \
        }                                                                            \
        cpasync16(base + OWH * 4 + d0, WH + gw0);                                    \
        cpasync16(base + OWH * 4 + d1, WH + gw1);                                    \
        if (WLO) {                                                                   \
            cpasync16(base + OWL * 4 + d0, WL + gw0);                                \
            cpasync16(base + OWL * 4 + d1, WL + gw1);                                \
        }                                                                            \
        asm volatile("cp.async.commit_group;");                                      \
    } while (0)

    COPY_CHUNK(0, 0);
    #pragma unroll
    for (int kc = 0; kc < 4; kc++) {
        if (kc < 3) {
            COPY_CHUNK(kc + 1, (kc + 1) & 1);
            asm volatile("cp.async.wait_group 1;");
        } else {
            asm volatile("cp.async.wait_group 0;");
        }
        __syncthreads();
        unsigned boff = (kc & 1) * (BUF * 4);
        #pragma unroll
        for (int s = 0; s < 2; s++) {
            unsigned soff = boff + s * 32;
            unsigned ah[2][4], al[2][4];
            ldsm4(ah[0], aHaddr[0] + soff);
            ldsm4(ah[1], aHaddr[1] + soff);
            if (SPLITA) {
                ldsm4(al[0], aLaddr[0] + soff);
                ldsm4(al[1], aLaddr[1] + soff);
            }
            #pragma unroll
            for (int q = 0; q < 4; q++) {
                unsigned bh[4], bl[4];
                ldsm4(bh, bHaddr[q] + soff);
                if (WLO) ldsm4(bl, bLaddr[q] + soff);
                #pragma unroll
                for (int mf = 0; mf < 2; mf++) {
                    mma16(acc[mf][2 * q], ah[mf], bh);
                    if (WLO) mma16(acc[mf][2 * q], ah[mf], bl);
                    if (SPLITA) mma16(acc[mf][2 * q], al[mf], bh);
                    mma16(acc[mf][2 * q + 1], ah[mf], bh + 2);
                    if (WLO) mma16(acc[mf][2 * q + 1], ah[mf], bl + 2);
                    if (SPLITA) mma16(acc[mf][2 * q + 1], al[mf], bh + 2);
                }
            }
        }
        __syncthreads();
    }
    #undef COPY_CHUNK
}

// --- fni/fnj GEMMs (1-term; outputs rounded to fp16 anyway); occ 3 for latency hiding ---
__global__ void __launch_bounds__(256, 3) k_mm2h(const unsigned* __restrict__ AH, int l,
                                                 unsigned* __restrict__ C0h,
                                                 unsigned* __restrict__ C1h) {
    int by = blockIdx.y;
    int m = by * 8 + l;
    int tid = threadIdx.x, lane = tid & 31, w = tid >> 5;
    int warp_m = w >> 1, warp_n = w & 1;
    int m0 = blockIdx.x * 128;
    float acc[2][8][4];
    #pragma unroll
    for (int mf = 0; mf < 2; mf++)
        #pragma unroll
        for (int nf = 0; nf < 8; nf++)
            #pragma unroll
            for (int r = 0; r < 4; r++) acc[mf][nf][r] = 0.f;
    mma_tile_t<1>(AH, nullptr, g_wpkh + m * 8192, nullptr, m0, acc, tid, lane, warp_m, warp_n);
    unsigned* Ch = (by == 0) ? C0h : C1h;
    #pragma unroll
    for (int mf = 0; mf < 2; mf++) {
        int rbase = m0 + warp_m * 32 + mf * 16 + (lane >> 2);
        #pragma unroll
        for (int nf = 0; nf < 8; nf++) {
            int col = warp_n * 64 + nf * 8 + 2 * (lane & 3);
            Ch[(size_t)rbase * 64 + (col >> 1)] = pack2(acc[mf][nf][0], acc[mf][nf][1]);
            Ch[(size_t)(rbase + 8) * 64 + (col >> 1)] = pack2(acc[mf][nf][2], acc[mf][nf][3]);
        }
    }
}

// --- hs GEMM (3-term exact; h-chain precision) ---
__global__ void __launch_bounds__(256, 2) k_mmhs(const unsigned* __restrict__ AH,
                                                 const unsigned* __restrict__ AL, int l,
                                                 float* __restrict__ C2) {
    int m = 16 + l;
    int tid = threadIdx.x, lane = tid & 31, w = tid >> 5;
    int warp_m = w >> 1, warp_n = w & 1;
    int m0 = blockIdx.x * 128;
    float acc[2][8][4];
    #pragma unroll
    for (int mf = 0; mf < 2; mf++)
        #pragma unroll
        for (int nf = 0; nf < 8; nf++)
            #pragma unroll
            for (int r = 0; r < 4; r++) acc[mf][nf][r] = 0.f;
    mma_tile_t<3>(AH, AL, g_wpkh + m * 8192, g_wpkl + m * 8192, m0, acc, tid, lane, warp_m, warp_n);
    #pragma unroll
    for (int mf = 0; mf < 2; mf++) {
        int rbase = m0 + warp_m * 32 + mf * 16 + (lane >> 2);
        #pragma unroll
        for (int nf = 0; nf < 8; nf++) {
            int col = warp_n * 64 + nf * 8 + 2 * (lane & 3);
            *(float2*)&C2[(size_t)rbase * 128 + col] = make_float2(acc[mf][nf][0], acc[mf][nf][1]);
            *(float2*)&C2[(size_t)(rbase + 8) * 128 + col] = make_float2(acc[mf][nf][2], acc[mf][nf][3]);
        }
    }
}

// --- single GEMM with bias + relu (final Wf, 3-term exact) ---
__global__ void __launch_bounds__(256, 2) k_mmbr(const unsigned* __restrict__ AH,
                                                 const unsigned* __restrict__ AL,
                                                 float* __restrict__ C,
                                                 const float* __restrict__ bias) {
    int tid = threadIdx.x, lane = tid & 31, w = tid >> 5;
    int warp_m = w >> 1, warp_n = w & 1;
    int m0 = blockIdx.x * 128;
    float acc[2][8][4];
    #pragma unroll
    for (int mf = 0; mf < 2; mf++)
        #pragma unroll
        for (int nf = 0; nf < 8; nf++)
            #pragma unroll
            for (int r = 0; r < 4; r++) acc[mf][nf][r] = 0.f;
    mma_tile_t<3>(AH, AL, g_wpkh + 32 * 8192, g_wpkl + 32 * 8192, m0, acc, tid, lane, warp_m, warp_n);
    #pragma unroll
    for (int mf = 0; mf < 2; mf++) {
        int rbase = m0 + warp_m * 32 + mf * 16 + (lane >> 2);
        #pragma unroll
        for (int nf = 0; nf < 8; nf++) {
            int col = warp_n * 64 + nf * 8 + 2 * (lane & 3);
            float b0 = __ldg(&bias[col]), b1 = __ldg(&bias[col + 1]);
            float2 lo = make_float2(fmaxf(acc[mf][nf][0] + b0, 0.f), fmaxf(acc[mf][nf][1] + b1, 0.f));
            float2 hi = make_float2(fmaxf(acc[mf][nf][2] + b0, 0.f), fmaxf(acc[mf][nf][3] + b1, 0.f));
            *(float2*)&C[(size_t)rbase * 128 + col] = lo;
            *(float2*)&C[(size_t)(rbase + 8) * 128 + col] = hi;
        }
    }
}

// --- fused edge kernel (layers 1..7): 1-term GEMM + gathers + leaky + attn-dot; occ 3 ---
__global__ void __launch_bounds__(256, 3) k_edge(const unsigned* __restrict__ EH, int l,
                                                 const float* __restrict__ bias,
                                                 const float* __restrict__ attn,
                                                 unsigned* __restrict__ FoutH,
                                                 const unsigned* __restrict__ fni16,
                                                 const unsigned* __restrict__ fnj16,
                                                 int writef) {
    float* ssc = (float*)(smem_u + 2 * 5120);
    int tid = threadIdx.x, lane = tid & 31, w = tid >> 5;
    int warp_m = w >> 1, warp_n = w & 1;
    int m0 = blockIdx.x * 128;
    if (tid < 128) ssc[tid] = 0.f;
    float acc[2][8][4];
    #pragma unroll
    for (int mf = 0; mf < 2; mf++)
        #pragma unroll
        for (int nf = 0; nf < 8; nf++)
            #pragma unroll
            for (int r = 0; r < 4; r++) acc[mf][nf][r] = 0.f;
    mma_tile_t<1>(EH, nullptr, g_wpkh + (24 + l) * 8192, nullptr,
                  m0, acc, tid, lane, warp_m, warp_n);

    float bia[8][2], att[8][2];
    #pragma unroll
    for (int nf = 0; nf < 8; nf++) {
        int col = warp_n * 64 + nf * 8 + 2 * (lane & 3);
        bia[nf][0] = __ldg(&bias[col]); bia[nf][1] = __ldg(&bias[col + 1]);
        att[nf][0] = __ldg(&attn[col]); att[nf][1] = __ldg(&attn[col + 1]);
    }

    #pragma unroll
    for (int mf = 0; mf < 2; mf++) {
        #pragma unroll
        for (int h = 0; h < 2; h++) {
            int rloc = warp_m * 32 + mf * 16 + (lane >> 2) + 8 * h;
            int e = m0 + rloc;
            int s = g_psrc[e], dt = g_pdst[e];
            const unsigned* fr = fni16 + (size_t)s * 64;
            const unsigned* gr = fnj16 + (size_t)dt * 64;
            float part = 0.f;
            #pragma unroll
            for (int nf = 0; nf < 8; nf++) {
                int col = warp_n * 64 + nf * 8 + 2 * (lane & 3);
                float2 fv = unpack2(__ldg(&fr[col >> 1]));
                float2 gv = unpack2(__ldg(&gr[col >> 1]));
                float v0 = acc[mf][nf][2 * h + 0] + fv.x + gv.x + bia[nf][0];
                float v1 = acc[mf][nf][2 * h + 1] + fv.y + gv.y + bia[nf][1];
                v0 = (v0 >= 0.f) ? v0 : 0.01f * v0;
                v1 = (v1 >= 0.f) ? v1 : 0.01f * v1;
                if (writef)
                    FoutH[(size_t)e * 64 + (col >> 1)] = pack2(v0, v1);
                part += v0 * att[nf][0] + v1 * att[nf][1];
            }
            part += __shfl_xor_sync(0xffffffffu, part, 1);
            part += __shfl_xor_sync(0xffffffffu, part, 2);
            if ((lane & 3) == 0) atomicAdd(&ssc[rloc], part);
        }
    }
    __syncthreads();
    if (tid < 128) g_score[m0 + tid] = ssc[tid];
}

// layer-0 edge kernel (permuted): gather table; fp16 fni/fnj
__global__ void k_edge_l0(const float* __restrict__ bias,
                          const float* __restrict__ attn,
                          unsigned* __restrict__ FoutH,
                          const unsigned* __restrict__ fni16,
                          const unsigned* __restrict__ fnj16) {
    int w = (blockIdx.x * blockDim.x + threadIdx.x) >> 5;
    int lane = threadIdx.x & 31;
    if (w >= EE) return;
    int te = g_ptoke[w], s = g_psrc[w], dt = g_pdst[w];
    float4 a = ((const float4*)g_embW)[te * 32 + lane];
    uint2 bu = ((const uint2*)(fni16 + (size_t)s * 64))[lane];
    uint2 cu = ((const uint2*)(fnj16 + (size_t)dt * 64))[lane];
    float2 b01 = unpack2(bu.x), b23 = unpack2(bu.y);
    float2 c01 = unpack2(cu.x), c23 = unpack2(cu.y);
    float4 bi = ((const float4*)bias)[lane];
    float4 at = ((const float4*)attn)[lane];
    float4 v;
    v.x = a.x + b01.x + c01.x + bi.x; v.x = (v.x >= 0.f) ? v.x : 0.01f * v.x;
    v.y = a.y + b01.y + c01.y + bi.y; v.y = (v.y >= 0.f) ? v.y : 0.01f * v.y;
    v.z = a.z + b23.x + c23.x + bi.z; v.z = (v.z >= 0.f) ? v.z : 0.01f * v.z;
    v.w = a.w + b23.y + c23.y + bi.w; v.w = (v.w >= 0.f) ? v.w : 0.01f * v.w;
    ((uint2*)FoutH)[(size_t)w * 32 + lane] = make_uint2(pack2(v.x, v.y), pack2(v.z, v.w));
    float part = v.x * at.x + v.y * at.y + v.z * at.z + v.w * at.w;
    #pragma unroll
    for (int off = 16; off; off >>= 1)
        part += __shfl_xor_sync(0xffffffffu, part, off);
    if (lane == 0) g_score[w] = part;
}

// ---------------- fused edge-softmax + aggregation + relu (2 warps per node) ----------------
// NOTE: s is uniform across lanes (every lane adds the same broadcast ex) -> NO lane reduction.
__global__ void k_agg(const float* __restrict__ hsrc,
                      unsigned* __restrict__ HoutH, unsigned* __restrict__ HoutL) {
    __shared__ float4 sacc[8][32];
    __shared__ float sms[8][2];
    int tid = threadIdx.x;
    int warp = tid >> 5, lane = tid & 31;
    int node = blockIdx.x * 4 + (warp >> 1);
    int half = warp & 1;
    int beg = g_rowstart[node], end = g_rowstart[node + 1];
    int cnt = end - beg;
    int mid = beg + ((cnt + 1) >> 1);
    int b0 = half ? mid : beg;
    int e0 = half ? end : mid;

    float mx = -3.4e38f;
    for (int i = b0 + lane; i < e0; i += 32)
        mx = fmaxf(mx, g_score[i]);
    #pragma unroll
    for (int off = 16; off; off >>= 1)
        mx = fmaxf(mx, __shfl_xor_sync(0xffffffffu, mx, off));

    float s = 0.f;
    float4 acc = make_float4(0.f, 0.f, 0.f, 0.f);
    for (int cb = b0; cb < e0; cb += 32) {
        int ce = min(cb + 32, e0);
        float ex0 = (cb + lane < ce) ? expf(g_score[cb + lane] - mx) : 0.f;
        for (int i = cb; i < ce; i++) {
            float ex = __shfl_sync(0xffffffffu, ex0, i - cb);
            s += ex;
            float4 hv = ((const float4*)hsrc)[g_psrc[i] * 32 + lane];
            acc.x += ex * hv.x; acc.y += ex * hv.y;
            acc.z += ex * hv.z; acc.w += ex * hv.w;
        }
    }
    // s already holds the full per-warp-segment sum on every lane (broadcast adds)

    sacc[warp][lane] = acc;
    if (lane == 0) { sms[warp][0] = mx; sms[warp][1] = s; }
    __syncthreads();

    if (half == 0) {
        float m1 = sms[warp + 1][0], s1 = sms[warp + 1][1];
        float4 acc1 = sacc[warp + 1][lane];
        float M = fmaxf(mx, m1);
        float sc0 = expf(mx - M), sc1 = expf(m1 - M);
        float stot = s * sc0 + s1 * sc1;
        acc.x = acc.x * sc0 + acc1.x * sc1;
        acc.y = acc.y * sc0 + acc1.y * sc1;
        acc.z = acc.z * sc0 + acc1.z * sc1;
        acc.w = acc.w * sc0 + acc1.w * sc1;
        if (stot > 0.f) {
            float inv = 1.0f / stot;
            acc.x *= inv; acc.y *= inv; acc.z *= inv; acc.w *= inv;
        } else {
            acc = make_float4(0.f, 0.f, 0.f, 0.f);
        }
        acc.x = fmaxf(acc.x, 0.f); acc.y = fmaxf(acc.y, 0.f);
        acc.z = fmaxf(acc.z, 0.f); acc.w = fmaxf(acc.w, 0.f);
        unsigned lo0, lo1;
        unsigned hi0 = packsplit(acc.x, acc.y, lo0);
        unsigned hi1 = packsplit(acc.z, acc.w, lo1);
        ((uint2*)HoutH)[node * 32 + lane] = make_uint2(hi0, hi1);
        ((uint2*)HoutL)[node * 32 + lane] = make_uint2(lo0, lo1);
    }
}

// ---------------- per-node bitonic sort of 128 features ----------------
__global__ void k_sort(const float* __restrict__ Hin, float* __restrict__ Hsort) {
    int w = (blockIdx.x * blockDim.x + threadIdx.x) >> 5;
    int lane = threadIdx.x & 31;
    if (w >= NN) return;
    float v[4];
    #pragma unroll
    for (int r = 0; r < 4; r++) v[r] = Hin[w * 128 + r * 32 + lane];
    for (int k = 2; k <= 128; k <<= 1) {
        for (int j = k >> 1; j; j >>= 1) {
            if (j < 32) {
                #pragma unroll
                for (int r = 0; r < 4; r++) {
                    int idx = r * 32 + lane;
                    float o = __shfl_xor_sync(0xffffffffu, v[r], j);
                    bool up = ((idx & k) == 0);
                    bool lower = ((idx & j) == 0);
                    v[r] = (lower == up) ? fminf(v[r], o) : fmaxf(v[r], o);
                }
            } else {
                int jr = j >> 5;
                #pragma unroll
                for (int r = 0; r < 4; r++) {
                    if ((r & jr) == 0) {
                        int r2 = r | jr;
                        bool up = (((r * 32) & k) == 0);
                        float a = v[r], b = v[r2];
                        float lo = fminf(a, b), hi = fmaxf(a, b);
                        v[r] = up ? lo : hi;
                        v[r2] = up ? hi : lo;
                    }
                }
            }
        }
    }
    #pragma unroll
    for (int r = 0; r < 4; r++) Hsort[w * 128 + r * 32 + lane] = v[r];
    float last = __shfl_sync(0xffffffffu, v[3], 31);
    if (lane == 0) g_lastch[w] = last;
}

// ---------------- top-32 nodes per graph ----------------
__global__ void k_topk() {
    __shared__ float cand[4][NPG];
    int wp = threadIdx.x >> 5, lane = threadIdx.x & 31;
    int b = blockIdx.x * 4 + wp;
    float* cn = cand[wp];
    for (int i = lane; i < NPG; i += 32) cn[i] = g_lastch[b * NPG + i];
    __syncwarp();
    for (int kk = 0; kk < KK; kk++) {
        float bv = -3.4e38f;
        int bi = 1 << 30;
        for (int i = lane; i < NPG; i += 32) {
            float v = cn[i];
            if (v > bv || (v == bv && i < bi)) { bv = v; bi = i; }
        }
        #pragma unroll
        for (int off = 16; off; off >>= 1) {
            float ov = __shfl_xor_sync(0xffffffffu, bv, off);
            int oi = __shfl_xor_sync(0xffffffffu, bi, off);
            if (ov > bv || (ov == bv && oi < bi)) { bv = ov; bi = oi; }
        }
        if (lane == 0) {
            g_topk[b * KK + kk] = b * NPG + bi;
            cn[bi] = -3.4e38f;
        }
        __syncwarp();
    }
}

// ---------------- ft = pooled @ W3; sl/sr ----------------
__global__ void k_ft(const float* __restrict__ W3, const float* __restrict__ al,
                     const float* __restrict__ ar, const float* __restrict__ Hsort) {
    __shared__ float pool[KK * DD];
    __shared__ float red[DD];
    int b = blockIdx.x, n = threadIdx.x;
    for (int kk = 0; kk < KK; kk++) {
        int node = g_topk[b * KK + kk];
        pool[kk * DD + n] = Hsort[node * DD + n];
    }
    __syncthreads();
    float acc = 0.f;
    #pragma unroll 8
    for (int i = 0; i < KK * DD; i++) acc += pool[i] * W3[i * DD + n];
    g_ft[b * DD + n] = acc;
    red[n] = acc * al[n];
    __syncthreads();
    for (int s = 64; s; s >>= 1) { if (n < s) red[n] += red[n + s]; __syncthreads(); }
    if (n == 0) g_sl[b] = red[0];
    __syncthreads();
    red[n] = acc * ar[n];
    __syncthreads();
    for (int s = 64; s; s >>= 1) { if (n < s) red[n] += red[n + s]; __syncthreads(); }
    if (n == 0) g_sr[b] = red[0];
}

// ---------------- graph-level GAT ----------------
__global__ void k_fg(const int* __restrict__ fgs, const int* __restrict__ fgd,
                     const float* __restrict__ b3) {
    int w = (blockIdx.x * blockDim.x + threadIdx.x) >> 5;
    int lane = threadIdx.x & 31;
    if (w >= BB) return;
    float srb = g_sr[w];
    float mx = -3.4e38f;
    for (int i = lane; i < EFE; i += 32) {
        if (fgd[i] == w) {
            float s = g_sl[fgs[i]] + srb;
            s = (s >= 0.f) ? s : 0.2f * s;
            mx = fmaxf(mx, s);
        }
    }
    #pragma unroll
    for (int off = 16; off; off >>= 1)
        mx = fmaxf(mx, __shfl_xor_sync(0xffffffffu, mx, off));
    float sm = 0.f;
    for (int i = lane; i < EFE; i += 32) {
        if (fgd[i] == w) {
            float s = g_sl[fgs[i]] + srb;
            s = (s >= 0.f) ? s : 0.2f * s;
            sm += expf(s - mx);
        }
    }
    #pragma unroll
    for (int off = 16; off; off >>= 1)
        sm += __shfl_xor_sync(0xffffffffu, sm, off);
    float4 acc = make_float4(0.f, 0.f, 0.f, 0.f);
    if (sm > 0.f) {
        float inv = 1.0f / sm;
        for (int i = 0; i < EFE; i++) {
            if (fgd[i] != w) continue;
            float s = g_sl[fgs[i]] + srb;
            s = (s >= 0.f) ? s : 0.2f * s;
            float coef = expf(s - mx) * inv;
            float4 f = ((const float4*)g_ft)[fgs[i] * 32 + lane];
            acc.x += coef * f.x; acc.y += coef * f.y;
            acc.z += coef * f.z; acc.w += coef * f.w;
        }
    }
    float4 bb = ((const float4*)b3)[lane];
    acc.x = fmaxf(acc.x + bb.x, 0.f); acc.y = fmaxf(acc.y + bb.y, 0.f);
    acc.z = fmaxf(acc.z + bb.z, 0.f); acc.w = fmaxf(acc.w + bb.w, 0.f);
    ((float4*)g_gv)[w * 32 + lane] = acc;
}

// ---------------- final ----------------
__global__ void k_final(const float* __restrict__ Wl, const float* __restrict__ bl,
                        const float* __restrict__ Wc, const float* __restrict__ bc,
                        float* __restrict__ out) {
    __shared__ float gs[DD];
    __shared__ float r0[DD], r1[DD];
    int b = blockIdx.x, n = threadIdx.x;
    gs[n] = g_gv[b * DD + n];
    __syncthreads();
    float acc = bl[n];
    #pragma unroll 8
    for (int k = 0; k < DD; k++) acc += gs[k] * Wl[k * DD + n];
    acc = fmaxf(acc, 0.f);
    r0[n] = acc * Wc[n * 2];
    r1[n] = acc * Wc[n * 2 + 1];
    __syncthreads();
    for (int s = 64; s; s >>= 1) {
        if (n < s) { r0[n] += r0[n + s]; r1[n] += r1[n + s]; }
        __syncthreads();
    }
    if (n == 0) {
        out[b * 2] = r0[0] + bc[0];
        out[b * 2 + 1] = r1[0] + bc[1];
    }
}

// ---------------- host ----------------
extern "C" void kernel_launch(void* const* d_in, const int* in_sizes, int n_in,
                              void* d_out, int out_size) {
    const int* tokens_h = (const int*)d_in[0];
    const int* tokens_e = (const int*)d_in[1];
    const int* src = (const int*)d_in[2];
    const int* dst = (const int*)d_in[3];
    const int* fg_src = (const int*)d_in[4];
    const int* fg_dst = (const int*)d_in[5];
    const float* token_emb = (const float*)d_in[6];
    const float* e_token_emb = (const float*)d_in[7];
    const float* W_ni = (const float*)d_in[8];
    const float* W_nj = (const float*)d_in[9];
    const float* W_fij = (const float*)d_in[10];
    const float* W_node = (const float*)d_in[11];
    const float* attn_e = (const float*)d_in[12];
    const float* bias_e = (const float*)d_in[13];
    const float* Wf = (const float*)d_in[14];
    const float* bf = (const float*)d_in[15];
    const float* W3 = (const float*)d_in[16];
    const float* al3 = (const float*)d_in[17];
    const float* ar3 = (const float*)d_in[18];
    const float* b3 = (const float*)d_in[19];
    const float* Wl = (const float*)d_in[20];
    const float* bl = (const float*)d_in[21];
    const float* Wc = (const float*)d_in[22];
    const float* bc = (const float*)d_in[23];
    float* out = (float*)d_out;

    unsigned *eph[2], *hph[2], *hpl[2], *fni16, *fnj16;
    float *hs, *hfin, *hsort;
    cudaGetSymbolAddress((void**)&eph[0], g_eph0);
    cudaGetSymbolAddress((void**)&eph[1], g_eph1);
    cudaGetSymbolAddress((void**)&hph[0], g_hph0);
    cudaGetSymbolAddress((void**)&hpl[0], g_hpl0);
    cudaGetSymbolAddress((void**)&hph[1], g_hph1);
    cudaGetSymbolAddress((void**)&hpl[1], g_hpl1);
    cudaGetSymbolAddress((void**)&fni16, g_fni16);
    cudaGetSymbolAddress((void**)&fnj16, g_fnj16);
    cudaGetSymbolAddress((void**)&hs, g_hs);
    cudaGetSymbolAddress((void**)&hfin, g_hfin);
    cudaGetSymbolAddress((void**)&hsort, g_hsort);

    cudaFuncSetAttribute(k_mm2h, cudaFuncAttributeMaxDynamicSharedMemorySize, SMEM_T1);
    cudaFuncSetAttribute(k_mmhs, cudaFuncAttributeMaxDynamicSharedMemorySize, SMEM_T3);
    cudaFuncSetAttribute(k_mmbr, cudaFuncAttributeMaxDynamicSharedMemorySize, SMEM_T3);
    cudaFuncSetAttribute(k_edge, cudaFuncAttributeMaxDynamicSharedMemorySize, SMEM_T1);
    cudaFuncSetAttribute(k_wpack, cudaFuncAttributeMaxDynamicSharedMemorySize, 129 * 128 * 4);

    // side stream + fork/join events (created once; no device memory involved)
    static cudaStream_t sB = nullptr;
    static cudaEvent_t evF = nullptr, evJ = nullptr;
    if (sB == nullptr) {
        cudaStreamCreateWithFlags(&sB, cudaStreamNonBlocking);
        cudaEventCreateWithFlags(&evF, cudaEventDisableTiming);
        cudaEventCreateWithFlags(&evJ, cudaEventDisableTiming);
    }
    cudaStream_t s0 = (cudaStream_t)0;

    // fork: CSR build + edge permutation on sB (independent of h-path setup)
    cudaEventRecord(evF, s0);
    cudaStreamWaitEvent(sB, evF, 0);
    k_zero_cursor<<<(NN + 255) / 256, 256, 0, sB>>>();
    k_count<<<(EE + 255) / 256, 256, 0, sB>>>(dst);
    k_scan<<<1, 1024, 0, sB>>>();
    k_copy_cursor<<<(NN + 255) / 256, 256, 0, sB>>>();
    k_scatter<<<(EE + 255) / 256, 256, 0, sB>>>(dst);
    k_permute<<<(EE + 255) / 256, 256, 0, sB>>>(src, dst, tokens_e);
    cudaEventRecord(evJ, sB);

    // main stream: h-path setup + layer-0 node GEMMs
    k_hinit<<<(NN * 32 + 255) / 256, 256>>>(tokens_h, token_emb);
    k_embw<<<100, 128>>>(e_token_emb, W_fij);
    k_wpack<<<33, 256, 129 * 128 * 4>>>(W_ni, W_nj, W_node, W_fij, Wf);

    dim3 g2(NN / 128, 2, 1);
    k_mm2h<<<g2, 256, SMEM_T1>>>(hph[0], 0, fni16, fnj16);
    k_mmhs<<<NN / 128, 256, SMEM_T3>>>(hph[0], hpl[0], 0, hs);

    // join: layer-0 edge kernel needs the permuted edge arrays
    cudaStreamWaitEvent(s0, evJ, 0);
    k_edge_l0<<<(EE * 32 + 255) / 256, 256>>>(bias_e, attn_e, eph[1], fni16, fnj16);
    k_agg<<<NN / 4, 256>>>(hs, hph[1], hpl[1]);

    for (int l = 1; l < LL; l++) {
        const float* bias_l = bias_e + l * DD;
        const float* attn_l = attn_e + l * DD;
        int hi = l & 1, ho = (l + 1) & 1;
        int writef = (l < LL - 1) ? 1 : 0;

        // fork after k_agg(l-1): hs GEMM overlaps with fni/fnj GEMM + edge kernel
        cudaEventRecord(evF, s0);
        cudaStreamWaitEvent(sB, evF, 0);
        k_mmhs<<<NN / 128, 256, SMEM_T3, sB>>>(hph[hi], hpl[hi], l, hs);
        cudaEventRecord(evJ, sB);

        k_mm2h<<<g2, 256, SMEM_T1>>>(hph[hi], l, fni16, fnj16);
        k_edge<<<EE / 128, 256, SMEM_T1>>>(eph[hi], l, bias_l, attn_l,
                                           eph[ho], fni16, fnj16, writef);

        // join before aggregation (needs hs)
        cudaStreamWaitEvent(s0, evJ, 0);
        k_agg<<<NN / 4, 256>>>(hs, hph[ho], hpl[ho]);
    }

    k_mmbr<<<NN / 128, 256, SMEM_T3>>>(hph[0], hpl[0], hfin, bf);
    k_sort<<<(NN * 32 + 255) / 256, 256>>>(hfin, hsort);
    k_topk<<<BB / 4, 128>>>();
    k_ft<<<BB, 128>>>(W3, al3, ar3, hsort);
    k_fg<<<(BB * 32 + 255) / 256, 256>>>(fg_src, fg_dst, b3);
    k_final<<<BB, 128>>>(Wl, bl, Wc, bc, out);
}

// round 15
// speedup vs baseline: 1.4592x; 1.4592x over previous
#include <cuda_runtime.h>
#include <cuda_fp16.h>

#define DD 128
#define NN 25600
#define EE 409600
#define BB 128
#define EFE 1024
#define LL 8
#define KK 32
#define NPG 200

// ---------------- scratch (device globals; allocation-free rule) ----------------
__device__ __align__(256) unsigned g_eph0[EE * 64];
__device__ __align__(256) unsigned g_eph1[EE * 64];
__device__ __align__(256) unsigned g_hph0[NN * 64];
__device__ __align__(256) unsigned g_hpl0[NN * 64];
__device__ __align__(256) unsigned g_hph1[NN * 64];
__device__ __align__(256) unsigned g_hpl1[NN * 64];
__device__ __align__(256) unsigned g_fni16[NN * 64];
__device__ __align__(256) unsigned g_fnj16[NN * 64];
__device__ __align__(256) float g_hs[NN * DD];
__device__ __align__(256) float g_hfin[NN * DD];
__device__ __align__(256) float g_hsort[NN * DD];
__device__ __align__(256) float g_score[EE];
__device__ __align__(256) float g_lastch[NN];
__device__ __align__(256) int   g_topk[BB * KK];
__device__ __align__(256) float g_ft[BB * DD];
__device__ __align__(256) float g_sl[BB];
__device__ __align__(256) float g_sr[BB];
__device__ __align__(256) float g_gv[BB * DD];
__device__ __align__(256) float g_embW[100 * DD];
__device__ __align__(256) int   g_cursor[NN];
__device__ __align__(256) int   g_rowstart[NN + 1];
__device__ __align__(256) int   g_perm[EE];
__device__ __align__(256) int   g_psrc[EE];
__device__ __align__(256) int   g_pdst[EE];
__device__ __align__(256) int   g_ptoke[EE];
__device__ __align__(256) unsigned g_wpkh[33 * 8192];
__device__ __align__(256) unsigned g_wpkl[33 * 8192];

// ---------------- helpers ----------------
__device__ __forceinline__ unsigned packsplit(float x0, float x1, unsigned& lo) {
    __half h0 = __float2half_rn(x0), h1 = __float2half_rn(x1);
    __half l0 = __float2half_rn(x0 - __half2float(h0));
    __half l1 = __float2half_rn(x1 - __half2float(h1));
    lo = ((unsigned)__half_as_ushort(l1) << 16) | (unsigned)__half_as_ushort(l0);
    return ((unsigned)__half_as_ushort(h1) << 16) | (unsigned)__half_as_ushort(h0);
}
__device__ __forceinline__ unsigned pack2(float x0, float x1) {
    __half2 h2 = __floats2half2_rn(x0, x1);
    return reinterpret_cast<unsigned&>(h2);
}
__device__ __forceinline__ float2 unpack2(unsigned u) {
    return __half22float2(reinterpret_cast<__half2&>(u));
}
__device__ __forceinline__ void mma16(float c[4], const unsigned a[4], const unsigned b[2]) {
    asm volatile(
        "mma.sync.aligned.m16n8k16.row.col.f32.f16.f16.f32 "
        "{%0,%1,%2,%3},{%4,%5,%6,%7},{%8,%9},{%0,%1,%2,%3};"
        : "+f"(c[0]), "+f"(c[1]), "+f"(c[2]), "+f"(c[3])
        : "r"(a[0]), "r"(a[1]), "r"(a[2]), "r"(a[3]), "r"(b[0]), "r"(b[1]));
}
__device__ __forceinline__ void ldsm4(unsigned r[4], unsigned addr) {
    asm volatile("ldmatrix.sync.aligned.m8n8.x4.shared.b16 {%0,%1,%2,%3}, [%4];"
        : "=r"(r[0]), "=r"(r[1]), "=r"(r[2]), "=r"(r[3]) : "r"(addr));
}
__device__ __forceinline__ void cpasync16(unsigned saddr, const void* g) {
    asm volatile("cp.async.ca.shared.global [%0], [%1], 16;" :: "r"(saddr), "l"(g));
}

// ---------------- CSR build + edge permutation ----------------
__global__ void k_zero_cursor() {
    int i = blockIdx.x * blockDim.x + threadIdx.x;
    if (i < NN) g_cursor[i] = 0;
}
__global__ void k_count(const int* __restrict__ dst) {
    int e = blockIdx.x * blockDim.x + threadIdx.x;
    if (e < EE) atomicAdd(&g_cursor[dst[e]], 1);
}
__global__ void k_scan() {
    __shared__ int s[1024];
    __shared__ int carry;
    int tid = threadIdx.x;
    if (tid == 0) carry = 0;
    __syncthreads();
    for (int base = 0; base < NN; base += 1024) {
        int i = base + tid;
        int v = (i < NN) ? g_cursor[i] : 0;
        s[tid] = v;
        __syncthreads();
        for (int off = 1; off < 1024; off <<= 1) {
            int t = (tid >= off) ? s[tid - off] : 0;
            __syncthreads();
            s[tid] += t;
            __syncthreads();
        }
        int excl = s[tid] - v;
        int bc = carry;
        if (i < NN) g_rowstart[i] = bc + excl;
        __syncthreads();
        if (tid == 0) carry = bc + s[1023];
        __syncthreads();
    }
    if (tid == 0) g_rowstart[NN] = carry;
}
__global__ void k_copy_cursor() {
    int i = blockIdx.x * blockDim.x + threadIdx.x;
    if (i < NN) g_cursor[i] = g_rowstart[i];
}
__global__ void k_scatter(const int* __restrict__ dst) {
    int e = blockIdx.x * blockDim.x + threadIdx.x;
    if (e < EE) {
        int p = atomicAdd(&g_cursor[dst[e]], 1);
        g_perm[p] = e;
    }
}
__global__ void k_permute(const int* __restrict__ src, const int* __restrict__ dst,
                          const int* __restrict__ toke) {
    int p = blockIdx.x * blockDim.x + threadIdx.x;
    if (p < EE) {
        int e = g_perm[p];
        g_psrc[p] = src[e];
        g_pdst[p] = dst[e];
        g_ptoke[p] = toke[e];
    }
}

// ---------------- init: h = relu(token_emb[tokens_h]) -> packed ----------------
__global__ void k_hinit(const int* __restrict__ tok, const float* __restrict__ emb) {
    int i = blockIdx.x * blockDim.x + threadIdx.x;
    if (i >= NN * 32) return;
    int n = i >> 5, c4 = i & 31;
    float4 v = ((const float4*)emb)[tok[n] * 32 + c4];
    v.x = fmaxf(v.x, 0.f); v.y = fmaxf(v.y, 0.f);
    v.z = fmaxf(v.z, 0.f); v.w = fmaxf(v.w, 0.f);
    unsigned lo0, lo1;
    unsigned hi0 = packsplit(v.x, v.y, lo0);
    unsigned hi1 = packsplit(v.z, v.w, lo1);
    ((uint2*)g_hph0)[n * 32 + c4] = make_uint2(hi0, hi1);
    ((uint2*)g_hpl0)[n * 32 + c4] = make_uint2(lo0, lo1);
}

__global__ void k_embw(const float* __restrict__ etok, const float* __restrict__ W) {
    int t = blockIdx.x, n = threadIdx.x;
    float acc = 0.f;
    #pragma unroll 8
    for (int k = 0; k < DD; k++) acc += etok[t * DD + k] * W[k * DD + n];
    g_embW[t * DD + n] = acc;
}

// ---------------- weight pre-pack ----------------
__global__ void k_wpack(const float* __restrict__ Wni, const float* __restrict__ Wnj,
                        const float* __restrict__ Wno, const float* __restrict__ Wfij,
                        const float* __restrict__ Wf) {
    extern __shared__ float sw[];
    int m = blockIdx.x, tid = threadIdx.x;
    const float* W = (m < 8) ? Wni + m * 16384
                   : (m < 16) ? Wnj + (m - 8) * 16384
                   : (m < 24) ? Wno + (m - 16) * 16384
                   : (m < 32) ? Wfij + (m - 24) * 16384
                   : Wf;
    for (int i = tid; i < 16384; i += 256) {
        int k = i >> 7, n = i & 127;
        sw[n * 129 + k] = W[i];
    }
    __syncthreads();
    int n = tid >> 1, ko = (tid & 1) * 64;
    #pragma unroll 8
    for (int p = 0; p < 32; p++) {
        int k = ko + 2 * p;
        float f0 = sw[n * 129 + k], f1 = sw[n * 129 + k + 1];
        unsigned lo;
        unsigned hi = packsplit(f0, f1, lo);
        g_wpkh[m * 8192 + n * 64 + (ko >> 1) + p] = hi;
        g_wpkl[m * 8192 + n * 64 + (ko >> 1) + p] = lo;
    }
}

// ================= split-fp16 tensor-core GEMM core =================
#define PADH 20
#define SMEM_T3 ((2 * 10240 + 128) * 4)
#define SMEM_T1 ((2 * 5120 + 128) * 4)

extern __shared__ unsigned smem_u[];

template <int TERMS>
__device__ __forceinline__ void mma_tile_t(const unsigned* __restrict__ AH,
                                           const unsigned* __restrict__ AL,
                                           const unsigned* __restrict__ WH,
                                           const unsigned* __restrict__ WL,
                                           int m0, float acc[2][8][4],
                                           int tid, int lane, int warp_m, int warp_n) {
    constexpr bool SPLITA = (TERMS == 3);
    constexpr bool WLO = (TERMS >= 2);
    constexpr unsigned OAL = 2560u;
    constexpr unsigned OWH = SPLITA ? 5120u : 2560u;
    constexpr unsigned OWL = OWH + 2560u;
    constexpr unsigned BUF = 2560u * (2 + (SPLITA ? 1 : 0) + (WLO ? 1 : 0));
    unsigned sb = (unsigned)__cvta_generic_to_shared(smem_u);
    int row_in = lane & 7, grp = lane >> 3;
    unsigned aHaddr[2], aLaddr[2];
    #pragma unroll
    for (int mf = 0; mf < 2; mf++) {
        int r = warp_m * 32 + mf * 16 + (grp & 1) * 8 + row_in;
        int p = (grp >> 1) * 4;
        aHaddr[mf] = sb + (r * PADH + p) * 4;
        if (SPLITA) aLaddr[mf] = sb + (OAL + r * PADH + p) * 4;
    }
    unsigned bHaddr[4], bLaddr[4];
    #pragma unroll
    for (int q = 0; q < 4; q++) {
        int n = warp_n * 64 + (2 * q + (grp >> 1)) * 8 + row_in;
        int p = (grp & 1) * 4;
        bHaddr[q] = sb + (OWH + n * PADH + p) * 4;
        if (WLO) bLaddr[q] = sb + (OWL + n * PADH + p) * 4;
    }
    int r0 = tid >> 2, c0 = tid & 3;
    int r1 = r0 + 64;

    #define COPY_CHUNK(kc, b) do {                                                   \
        unsigned base = sb + (b) * (BUF * 4);                                        \
        unsigned d0 = (r0 * PADH + c0 * 4) * 4, d1 = (r1 * PADH + c0 * 4) * 4;       \
        size_t ga0 = (size_t)(m0 + r0) * 64 + (kc) * 16 + c0 * 4;                    \
        size_t ga1 = (size_t)(m0 + r1) * 64 + (kc) * 16 + c0 * 4;                    \
        size_t gw0 = (size_t)r0 * 64 + (kc) * 16 + c0 * 4;                           \
        size_t gw1 = (size_t)r1 * 64 + (kc) * 16 + c0 * 4;                           \
        cpasync16(base + d0, AH + ga0);                                              \
        cpasync16(base + d1, AH + ga1);                                              \
        if (SPLITA) {                                                                \
            cpasync16(base + OAL * 4 + d0, AL + ga0);                                \
            cpasync16(base + OAL * 4 + d1, AL + ga1);                                \
        }                                                                            \
        cpasync16(base + OWH * 4 + d0, WH + gw0);                                    \
        cpasync16(base + OWH * 4 + d1, WH + gw1);                                    \
        if (WLO) {                                                                   \
            cpasync16(base + OWL * 4 + d0, WL + gw0);                                \
            cpasync16(base + OWL * 4 + d1, WL + gw1);                                \
        }                                                                            \
        asm volatile("cp.async.commit_group;");                                      \
    } while (0)

    COPY_CHUNK(0, 0);
    #pragma unroll
    for (int kc = 0; kc < 4; kc++) {
        if (kc < 3) {
            COPY_CHUNK(kc + 1, (kc + 1) & 1);
            asm volatile("cp.async.wait_group 1;");
        } else {
            asm volatile("cp.async.wait_group 0;");
        }
        __syncthreads();
        unsigned boff = (kc & 1) * (BUF * 4);
        #pragma unroll
        for (int s = 0; s < 2; s++) {
            unsigned soff = boff + s * 32;
            unsigned ah[2][4], al[2][4];
            ldsm4(ah[0], aHaddr[0] + soff);
            ldsm4(ah[1], aHaddr[1] + soff);
            if (SPLITA) {
                ldsm4(al[0], aLaddr[0] + soff);
                ldsm4(al[1], aLaddr[1] + soff);
            }
            #pragma unroll
            for (int q = 0; q < 4; q++) {
                unsigned bh[4], bl[4];
                ldsm4(bh, bHaddr[q] + soff);
                if (WLO) ldsm4(bl, bLaddr[q] + soff);
                #pragma unroll
                for (int mf = 0; mf < 2; mf++) {
                    mma16(acc[mf][2 * q], ah[mf], bh);
                    if (WLO) mma16(acc[mf][2 * q], ah[mf], bl);
                    if (SPLITA) mma16(acc[mf][2 * q], al[mf], bh);
                    mma16(acc[mf][2 * q + 1], ah[mf], bh + 2);
                    if (WLO) mma16(acc[mf][2 * q + 1], ah[mf], bl + 2);
                    if (SPLITA) mma16(acc[mf][2 * q + 1], al[mf], bh + 2);
                }
            }
        }
        __syncthreads();
    }
    #undef COPY_CHUNK
}

// --- fni/fnj GEMMs (1-term; outputs rounded to fp16 anyway) ---
__global__ void __launch_bounds__(256, 2) k_mm2h(const unsigned* __restrict__ AH, int l,
                                                 unsigned* __restrict__ C0h,
                                                 unsigned* __restrict__ C1h) {
    int by = blockIdx.y;
    int m = by * 8 + l;
    int tid = threadIdx.x, lane = tid & 31, w = tid >> 5;
    int warp_m = w >> 1, warp_n = w & 1;
    int m0 = blockIdx.x * 128;
    float acc[2][8][4];
    #pragma unroll
    for (int mf = 0; mf < 2; mf++)
        #pragma unroll
        for (int nf = 0; nf < 8; nf++)
            #pragma unroll
            for (int r = 0; r < 4; r++) acc[mf][nf][r] = 0.f;
    mma_tile_t<1>(AH, nullptr, g_wpkh + m * 8192, nullptr, m0, acc, tid, lane, warp_m, warp_n);
    unsigned* Ch = (by == 0) ? C0h : C1h;
    #pragma unroll
    for (int mf = 0; mf < 2; mf++) {
        int rbase = m0 + warp_m * 32 + mf * 16 + (lane >> 2);
        #pragma unroll
        for (int nf = 0; nf < 8; nf++) {
            int col = warp_n * 64 + nf * 8 + 2 * (lane & 3);
            Ch[(size_t)rbase * 64 + (col >> 1)] = pack2(acc[mf][nf][0], acc[mf][nf][1]);
            Ch[(size_t)(rbase + 8) * 64 + (col >> 1)] = pack2(acc[mf][nf][2], acc[mf][nf][3]);
        }
    }
}

// --- hs GEMM (3-term exact; h-chain precision) ---
__global__ void __launch_bounds__(256, 2) k_mmhs(const unsigned* __restrict__ AH,
                                                 const unsigned* __restrict__ AL, int l,
                                                 float* __restrict__ C2) {
    int m = 16 + l;
    int tid = threadIdx.x, lane = tid & 31, w = tid >> 5;
    int warp_m = w >> 1, warp_n = w & 1;
    int m0 = blockIdx.x * 128;
    float acc[2][8][4];
    #pragma unroll
    for (int mf = 0; mf < 2; mf++)
        #pragma unroll
        for (int nf = 0; nf < 8; nf++)
            #pragma unroll
            for (int r = 0; r < 4; r++) acc[mf][nf][r] = 0.f;
    mma_tile_t<3>(AH, AL, g_wpkh + m * 8192, g_wpkl + m * 8192, m0, acc, tid, lane, warp_m, warp_n);
    #pragma unroll
    for (int mf = 0; mf < 2; mf++) {
        int rbase = m0 + warp_m * 32 + mf * 16 + (lane >> 2);
        #pragma unroll
        for (int nf = 0; nf < 8; nf++) {
            int col = warp_n * 64 + nf * 8 + 2 * (lane & 3);
            *(float2*)&C2[(size_t)rbase * 128 + col] = make_float2(acc[mf][nf][0], acc[mf][nf][1]);
            *(float2*)&C2[(size_t)(rbase + 8) * 128 + col] = make_float2(acc[mf][nf][2], acc[mf][nf][3]);
        }
    }
}

// --- single GEMM with bias + relu (final Wf, 3-term exact) ---
__global__ void __launch_bounds__(256, 2) k_mmbr(const unsigned* __restrict__ AH,
                                                 const unsigned* __restrict__ AL,
                                                 float* __restrict__ C,
                                                 const float* __restrict__ bias) {
    int tid = threadIdx.x, lane = tid & 31, w = tid >> 5;
    int warp_m = w >> 1, warp_n = w & 1;
    int m0 = blockIdx.x * 128;
    float acc[2][8][4];
    #pragma unroll
    for (int mf = 0; mf < 2; mf++)
        #pragma unroll
        for (int nf = 0; nf < 8; nf++)
            #pragma unroll
            for (int r = 0; r < 4; r++) acc[mf][nf][r] = 0.f;
    mma_tile_t<3>(AH, AL, g_wpkh + 32 * 8192, g_wpkl + 32 * 8192, m0, acc, tid, lane, warp_m, warp_n);
    #pragma unroll
    for (int mf = 0; mf < 2; mf++) {
        int rbase = m0 + warp_m * 32 + mf * 16 + (lane >> 2);
        #pragma unroll
        for (int nf = 0; nf < 8; nf++) {
            int col = warp_n * 64 + nf * 8 + 2 * (lane & 3);
            float b0 = __ldg(&bias[col]), b1 = __ldg(&bias[col + 1]);
            float2 lo = make_float2(fmaxf(acc[mf][nf][0] + b0, 0.f), fmaxf(acc[mf][nf][1] + b1, 0.f));
            float2 hi = make_float2(fmaxf(acc[mf][nf][2] + b0, 0.f), fmaxf(acc[mf][nf][3] + b1, 0.f));
            *(float2*)&C[(size_t)rbase * 128 + col] = lo;
            *(float2*)&C[(size_t)(rbase + 8) * 128 + col] = hi;
        }
    }
}

// --- fused edge kernel (layers 1..7): 1-term GEMM + gathers + leaky + attn-dot ---
__global__ void __launch_bounds__(256, 2) k_edge(const unsigned* __restrict__ EH, int l,
                                                 const float* __restrict__ bias,
                                                 const float* __restrict__ attn,
                                                 unsigned* __restrict__ FoutH,
                                                 const unsigned* __restrict__ fni16,
                                                 const unsigned* __restrict__ fnj16,
                                                 int writef) {
    float* ssc = (float*)(smem_u + 2 * 5120);
    int tid = threadIdx.x, lane = tid & 31, w = tid >> 5;
    int warp_m = w >> 1, warp_n = w & 1;
    int m0 = blockIdx.x * 128;
    if (tid < 128) ssc[tid] = 0.f;
    float acc[2][8][4];
    #pragma unroll
    for (int mf = 0; mf < 2; mf++)
        #pragma unroll
        for (int nf = 0; nf < 8; nf++)
            #pragma unroll
            for (int r = 0; r < 4; r++) acc[mf][nf][r] = 0.f;
    mma_tile_t<1>(EH, nullptr, g_wpkh + (24 + l) * 8192, nullptr,
                  m0, acc, tid, lane, warp_m, warp_n);

    float bia[8][2], att[8][2];
    #pragma unroll
    for (int nf = 0; nf < 8; nf++) {
        int col = warp_n * 64 + nf * 8 + 2 * (lane & 3);
        bia[nf][0] = __ldg(&bias[col]); bia[nf][1] = __ldg(&bias[col + 1]);
        att[nf][0] = __ldg(&attn[col]); att[nf][1] = __ldg(&attn[col + 1]);
    }

    #pragma unroll
    for (int mf = 0; mf < 2; mf++) {
        #pragma unroll
        for (int h = 0; h < 2; h++) {
            int rloc = warp_m * 32 + mf * 16 + (lane >> 2) + 8 * h;
            int e = m0 + rloc;
            int s = g_psrc[e], dt = g_pdst[e];
            const unsigned* fr = fni16 + (size_t)s * 64;
            const unsigned* gr = fnj16 + (size_t)dt * 64;
            float part = 0.f;
            #pragma unroll
            for (int nf = 0; nf < 8; nf++) {
                int col = warp_n * 64 + nf * 8 + 2 * (lane & 3);
                float2 fv = unpack2(__ldg(&fr[col >> 1]));
                float2 gv = unpack2(__ldg(&gr[col >> 1]));
                float v0 = acc[mf][nf][2 * h + 0] + fv.x + gv.x + bia[nf][0];
                float v1 = acc[mf][nf][2 * h + 1] + fv.y + gv.y + bia[nf][1];
                v0 = (v0 >= 0.f) ? v0 : 0.01f * v0;
                v1 = (v1 >= 0.f) ? v1 : 0.01f * v1;
                if (writef)
                    FoutH[(size_t)e * 64 + (col >> 1)] = pack2(v0, v1);
                part += v0 * att[nf][0] + v1 * att[nf][1];
            }
            part += __shfl_xor_sync(0xffffffffu, part, 1);
            part += __shfl_xor_sync(0xffffffffu, part, 2);
            if ((lane & 3) == 0) atomicAdd(&ssc[rloc], part);
        }
    }
    __syncthreads();
    if (tid < 128) g_score[m0 + tid] = ssc[tid];
}

// layer-0 edge kernel (permuted): gather table; fp16 fni/fnj
__global__ void k_edge_l0(const float* __restrict__ bias,
                          const float* __restrict__ attn,
                          unsigned* __restrict__ FoutH,
                          const unsigned* __restrict__ fni16,
                          const unsigned* __restrict__ fnj16) {
    int w = (blockIdx.x * blockDim.x + threadIdx.x) >> 5;
    int lane = threadIdx.x & 31;
    if (w >= EE) return;
    int te = g_ptoke[w], s = g_psrc[w], dt = g_pdst[w];
    float4 a = ((const float4*)g_embW)[te * 32 + lane];
    uint2 bu = ((const uint2*)(fni16 + (size_t)s * 64))[lane];
    uint2 cu = ((const uint2*)(fnj16 + (size_t)dt * 64))[lane];
    float2 b01 = unpack2(bu.x), b23 = unpack2(bu.y);
    float2 c01 = unpack2(cu.x), c23 = unpack2(cu.y);
    float4 bi = ((const float4*)bias)[lane];
    float4 at = ((const float4*)attn)[lane];
    float4 v;
    v.x = a.x + b01.x + c01.x + bi.x; v.x = (v.x >= 0.f) ? v.x : 0.01f * v.x;
    v.y = a.y + b01.y + c01.y + bi.y; v.y = (v.y >= 0.f) ? v.y : 0.01f * v.y;
    v.z = a.z + b23.x + c23.x + bi.z; v.z = (v.z >= 0.f) ? v.z : 0.01f * v.z;
    v.w = a.w + b23.y + c23.y + bi.w; v.w = (v.w >= 0.f) ? v.w : 0.01f * v.w;
    ((uint2*)FoutH)[(size_t)w * 32 + lane] = make_uint2(pack2(v.x, v.y), pack2(v.z, v.w));
    float part = v.x * at.x + v.y * at.y + v.z * at.z + v.w * at.w;
    #pragma unroll
    for (int off = 16; off; off >>= 1)
        part += __shfl_xor_sync(0xffffffffu, part, off);
    if (lane == 0) g_score[w] = part;
}

// ---------------- fused edge-softmax + aggregation + relu (2 warps per node) ----------------
// s is uniform across lanes (broadcast adds) -> no lane reduction needed.
__global__ void k_agg(const float* __restrict__ hsrc,
                      unsigned* __restrict__ HoutH, unsigned* __restrict__ HoutL) {
    __shared__ float4 sacc[8][32];
    __shared__ float sms[8][2];
    int tid = threadIdx.x;
    int warp = tid >> 5, lane = tid & 31;
    int node = blockIdx.x * 4 + (warp >> 1);
    int half = warp & 1;
    int beg = g_rowstart[node], end = g_rowstart[node + 1];
    int cnt = end - beg;
    int mid = beg + ((cnt + 1) >> 1);
    int b0 = half ? mid : beg;
    int e0 = half ? end : mid;

    float mx = -3.4e38f;
    for (int i = b0 + lane; i < e0; i += 32)
        mx = fmaxf(mx, g_score[i]);
    #pragma unroll
    for (int off = 16; off; off >>= 1)
        mx = fmaxf(mx, __shfl_xor_sync(0xffffffffu, mx, off));

    float s = 0.f;
    float4 acc = make_float4(0.f, 0.f, 0.f, 0.f);
    for (int cb = b0; cb < e0; cb += 32) {
        int ce = min(cb + 32, e0);
        float ex0 = (cb + lane < ce) ? expf(g_score[cb + lane] - mx) : 0.f;
        for (int i = cb; i < ce; i++) {
            float ex = __shfl_sync(0xffffffffu, ex0, i - cb);
            s += ex;
            float4 hv = ((const float4*)hsrc)[g_psrc[i] * 32 + lane];
            acc.x += ex * hv.x; acc.y += ex * hv.y;
            acc.z += ex * hv.z; acc.w += ex * hv.w;
        }
    }

    sacc[warp][lane] = acc;
    if (lane == 0) { sms[warp][0] = mx; sms[warp][1] = s; }
    __syncthreads();

    if (half == 0) {
        float m1 = sms[warp + 1][0], s1 = sms[warp + 1][1];
        float4 acc1 = sacc[warp + 1][lane];
        float M = fmaxf(mx, m1);
        float sc0 = expf(mx - M), sc1 = expf(m1 - M);
        float stot = s * sc0 + s1 * sc1;
        acc.x = acc.x * sc0 + acc1.x * sc1;
        acc.y = acc.y * sc0 + acc1.y * sc1;
        acc.z = acc.z * sc0 + acc1.z * sc1;
        acc.w = acc.w * sc0 + acc1.w * sc1;
        if (stot > 0.f) {
            float inv = 1.0f / stot;
            acc.x *= inv; acc.y *= inv; acc.z *= inv; acc.w *= inv;
        } else {
            acc = make_float4(0.f, 0.f, 0.f, 0.f);
        }
        acc.x = fmaxf(acc.x, 0.f); acc.y = fmaxf(acc.y, 0.f);
        acc.z = fmaxf(acc.z, 0.f); acc.w = fmaxf(acc.w, 0.f);
        unsigned lo0, lo1;
        unsigned hi0 = packsplit(acc.x, acc.y, lo0);
        unsigned hi1 = packsplit(acc.z, acc.w, lo1);
        ((uint2*)HoutH)[node * 32 + lane] = make_uint2(hi0, hi1);
        ((uint2*)HoutL)[node * 32 + lane] = make_uint2(lo0, lo1);
    }
}

// ---------------- per-node bitonic sort of 128 features ----------------
__global__ void k_sort(const float* __restrict__ Hin, float* __restrict__ Hsort) {
    int w = (blockIdx.x * blockDim.x + threadIdx.x) >> 5;
    int lane = threadIdx.x & 31;
    if (w >= NN) return;
    float v[4];
    #pragma unroll
    for (int r = 0; r < 4; r++) v[r] = Hin[w * 128 + r * 32 + lane];
    for (int k = 2; k <= 128; k <<= 1) {
        for (int j = k >> 1; j; j >>= 1) {
            if (j < 32) {
                #pragma unroll
                for (int r = 0; r < 4; r++) {
                    int idx = r * 32 + lane;
                    float o = __shfl_xor_sync(0xffffffffu, v[r], j);
                    bool up = ((idx & k) == 0);
                    bool lower = ((idx & j) == 0);
                    v[r] = (lower == up) ? fminf(v[r], o) : fmaxf(v[r], o);
                }
            } else {
                int jr = j >> 5;
                #pragma unroll
                for (int r = 0; r < 4; r++) {
                    if ((r & jr) == 0) {
                        int r2 = r | jr;
                        bool up = (((r * 32) & k) == 0);
                        float a = v[r], b = v[r2];
                        float lo = fminf(a, b), hi = fmaxf(a, b);
                        v[r] = up ? lo : hi;
                        v[r2] = up ? hi : lo;
                    }
                }
            }
        }
    }
    #pragma unroll
    for (int r = 0; r < 4; r++) Hsort[w * 128 + r * 32 + lane] = v[r];
    float last = __shfl_sync(0xffffffffu, v[3], 31);
    if (lane == 0) g_lastch[w] = last;
}

// ---------------- top-32 nodes per graph ----------------
__global__ void k_topk() {
    __shared__ float cand[4][NPG];
    int wp = threadIdx.x >> 5, lane = threadIdx.x & 31;
    int b = blockIdx.x * 4 + wp;
    float* cn = cand[wp];
    for (int i = lane; i < NPG; i += 32) cn[i] = g_lastch[b * NPG + i];
    __syncwarp();
    for (int kk = 0; kk < KK; kk++) {
        float bv = -3.4e38f;
        int bi = 1 << 30;
        for (int i = lane; i < NPG; i += 32) {
            float v = cn[i];
            if (v > bv || (v == bv && i < bi)) { bv = v; bi = i; }
        }
        #pragma unroll
        for (int off = 16; off; off >>= 1) {
            float ov = __shfl_xor_sync(0xffffffffu, bv, off);
            int oi = __shfl_xor_sync(0xffffffffu, bi, off);
            if (ov > bv || (ov == bv && oi < bi)) { bv = ov; bi = oi; }
        }
        if (lane == 0) {
            g_topk[b * KK + kk] = b * NPG + bi;
            cn[bi] = -3.4e38f;
        }
        __syncwarp();
    }
}

// ---------------- ft = pooled @ W3; sl/sr ----------------
__global__ void k_ft(const float* __restrict__ W3, const float* __restrict__ al,
                     const float* __restrict__ ar, const float* __restrict__ Hsort) {
    __shared__ float pool[KK * DD];
    __shared__ float red[DD];
    int b = blockIdx.x, n = threadIdx.x;
    for (int kk = 0; kk < KK; kk++) {
        int node = g_topk[b * KK + kk];
        pool[kk * DD + n] = Hsort[node * DD + n];
    }
    __syncthreads();
    float acc = 0.f;
    #pragma unroll 8
    for (int i = 0; i < KK * DD; i++) acc += pool[i] * W3[i * DD + n];
    g_ft[b * DD + n] = acc;
    red[n] = acc * al[n];
    __syncthreads();
    for (int s = 64; s; s >>= 1) { if (n < s) red[n] += red[n + s]; __syncthreads(); }
    if (n == 0) g_sl[b] = red[0];
    __syncthreads();
    red[n] = acc * ar[n];
    __syncthreads();
    for (int s = 64; s; s >>= 1) { if (n < s) red[n] += red[n + s]; __syncthreads(); }
    if (n == 0) g_sr[b] = red[0];
}

// ---------------- graph-level GAT ----------------
__global__ void k_fg(const int* __restrict__ fgs, const int* __restrict__ fgd,
                     const float* __restrict__ b3) {
    int w = (blockIdx.x * blockDim.x + threadIdx.x) >> 5;
    int lane = threadIdx.x & 31;
    if (w >= BB) return;
    float srb = g_sr[w];
    float mx = -3.4e38f;
    for (int i = lane; i < EFE; i += 32) {
        if (fgd[i] == w) {
            float s = g_sl[fgs[i]] + srb;
            s = (s >= 0.f) ? s : 0.2f * s;
            mx = fmaxf(mx, s);
        }
    }
    #pragma unroll
    for (int off = 16; off; off >>= 1)
        mx = fmaxf(mx, __shfl_xor_sync(0xffffffffu, mx, off));
    float sm = 0.f;
    for (int i = lane; i < EFE; i += 32) {
        if (fgd[i] == w) {
            float s = g_sl[fgs[i]] + srb;
            s = (s >= 0.f) ? s : 0.2f * s;
            sm += expf(s - mx);
        }
    }
    #pragma unroll
    for (int off = 16; off; off >>= 1)
        sm += __shfl_xor_sync(0xffffffffu, sm, off);
    float4 acc = make_float4(0.f, 0.f, 0.f, 0.f);
    if (sm > 0.f) {
        float inv = 1.0f / sm;
        for (int i = 0; i < EFE; i++) {
            if (fgd[i] != w) continue;
            float s = g_sl[fgs[i]] + srb;
            s = (s >= 0.f) ? s : 0.2f * s;
            float coef = expf(s - mx) * inv;
            float4 f = ((const float4*)g_ft)[fgs[i] * 32 + lane];
            acc.x += coef * f.x; acc.y += coef * f.y;
            acc.z += coef * f.z; acc.w += coef * f.w;
        }
    }
    float4 bb = ((const float4*)b3)[lane];
    acc.x = fmaxf(acc.x + bb.x, 0.f); acc.y = fmaxf(acc.y + bb.y, 0.f);
    acc.z = fmaxf(acc.z + bb.z, 0.f); acc.w = fmaxf(acc.w + bb.w, 0.f);
    ((float4*)g_gv)[w * 32 + lane] = acc;
}

// ---------------- final ----------------
__global__ void k_final(const float* __restrict__ Wl, const float* __restrict__ bl,
                        const float* __restrict__ Wc, const float* __restrict__ bc,
                        float* __restrict__ out) {
    __shared__ float gs[DD];
    __shared__ float r0[DD], r1[DD];
    int b = blockIdx.x, n = threadIdx.x;
    gs[n] = g_gv[b * DD + n];
    __syncthreads();
    float acc = bl[n];
    #pragma unroll 8
    for (int k = 0; k < DD; k++) acc += gs[k] * Wl[k * DD + n];
    acc = fmaxf(acc, 0.f);
    r0[n] = acc * Wc[n * 2];
    r1[n] = acc * Wc[n * 2 + 1];
    __syncthreads();
    for (int s = 64; s; s >>= 1) {
        if (n < s) { r0[n] += r0[n + s]; r1[n] += r1[n + s]; }
        __syncthreads();
    }
    if (n == 0) {
        out[b * 2] = r0[0] + bc[0];
        out[b * 2 + 1] = r1[0] + bc[1];
    }
}

// ---------------- host ----------------
extern "C" void kernel_launch(void* const* d_in, const int* in_sizes, int n_in,
                              void* d_out, int out_size) {
    const int* tokens_h = (const int*)d_in[0];
    const int* tokens_e = (const int*)d_in[1];
    const int* src = (const int*)d_in[2];
    const int* dst = (const int*)d_in[3];
    const int* fg_src = (const int*)d_in[4];
    const int* fg_dst = (const int*)d_in[5];
    const float* token_emb = (const float*)d_in[6];
    const float* e_token_emb = (const float*)d_in[7];
    const float* W_ni = (const float*)d_in[8];
    const float* W_nj = (const float*)d_in[9];
    const float* W_fij = (const float*)d_in[10];
    const float* W_node = (const float*)d_in[11];
    const float* attn_e = (const float*)d_in[12];
    const float* bias_e = (const float*)d_in[13];
    const float* Wf = (const float*)d_in[14];
    const float* bf = (const float*)d_in[15];
    const float* W3 = (const float*)d_in[16];
    const float* al3 = (const float*)d_in[17];
    const float* ar3 = (const float*)d_in[18];
    const float* b3 = (const float*)d_in[19];
    const float* Wl = (const float*)d_in[20];
    const float* bl = (const float*)d_in[21];
    const float* Wc = (const float*)d_in[22];
    const float* bc = (const float*)d_in[23];
    float* out = (float*)d_out;

    unsigned *eph[2], *hph[2], *hpl[2], *fni16, *fnj16;
    float *hs, *hfin, *hsort;
    cudaGetSymbolAddress((void**)&eph[0], g_eph0);
    cudaGetSymbolAddress((void**)&eph[1], g_eph1);
    cudaGetSymbolAddress((void**)&hph[0], g_hph0);
    cudaGetSymbolAddress((void**)&hpl[0], g_hpl0);
    cudaGetSymbolAddress((void**)&hph[1], g_hph1);
    cudaGetSymbolAddress((void**)&hpl[1], g_hpl1);
    cudaGetSymbolAddress((void**)&fni16, g_fni16);
    cudaGetSymbolAddress((void**)&fnj16, g_fnj16);
    cudaGetSymbolAddress((void**)&hs, g_hs);
    cudaGetSymbolAddress((void**)&hfin, g_hfin);
    cudaGetSymbolAddress((void**)&hsort, g_hsort);

    cudaFuncSetAttribute(k_mm2h, cudaFuncAttributeMaxDynamicSharedMemorySize, SMEM_T1);
    cudaFuncSetAttribute(k_mmhs, cudaFuncAttributeMaxDynamicSharedMemorySize, SMEM_T3);
    cudaFuncSetAttribute(k_mmbr, cudaFuncAttributeMaxDynamicSharedMemorySize, SMEM_T3);
    cudaFuncSetAttribute(k_edge, cudaFuncAttributeMaxDynamicSharedMemorySize, SMEM_T1);
    cudaFuncSetAttribute(k_wpack, cudaFuncAttributeMaxDynamicSharedMemorySize, 129 * 128 * 4);

    // side stream + fork/join events (created once; no device memory involved)
    static cudaStream_t sB = nullptr;
    static cudaEvent_t evF = nullptr, evJ = nullptr;
    if (sB == nullptr) {
        cudaStreamCreateWithFlags(&sB, cudaStreamNonBlocking);
        cudaEventCreateWithFlags(&evF, cudaEventDisableTiming);
        cudaEventCreateWithFlags(&evJ, cudaEventDisableTiming);
    }
    cudaStream_t s0 = (cudaStream_t)0;

    // fork: CSR build + edge permutation on sB (independent of h-path setup)
    cudaEventRecord(evF, s0);
    cudaStreamWaitEvent(sB, evF, 0);
    k_zero_cursor<<<(NN + 255) / 256, 256, 0, sB>>>();
    k_count<<<(EE + 255) / 256, 256, 0, sB>>>(dst);
    k_scan<<<1, 1024, 0, sB>>>();
    k_copy_cursor<<<(NN + 255) / 256, 256, 0, sB>>>();
    k_scatter<<<(EE + 255) / 256, 256, 0, sB>>>(dst);
    k_permute<<<(EE + 255) / 256, 256, 0, sB>>>(src, dst, tokens_e);
    cudaEventRecord(evJ, sB);

    // main stream: h-path setup + layer-0 node GEMMs
    k_hinit<<<(NN * 32 + 255) / 256, 256>>>(tokens_h, token_emb);
    k_embw<<<100, 128>>>(e_token_emb, W_fij);
    k_wpack<<<33, 256, 129 * 128 * 4>>>(W_ni, W_nj, W_node, W_fij, Wf);

    dim3 g2(NN / 128, 2, 1);
    k_mm2h<<<g2, 256, SMEM_T1>>>(hph[0], 0, fni16, fnj16);
    k_mmhs<<<NN / 128, 256, SMEM_T3>>>(hph[0], hpl[0], 0, hs);

    // join: layer-0 edge kernel needs the permuted edge arrays
    cudaStreamWaitEvent(s0, evJ, 0);
    k_edge_l0<<<(EE * 32 + 255) / 256, 256>>>(bias_e, attn_e, eph[1], fni16, fnj16);
    k_agg<<<NN / 4, 256>>>(hs, hph[1], hpl[1]);

    for (int l = 1; l < LL; l++) {
        const float* bias_l = bias_e + l * DD;
        const float* attn_l = attn_e + l * DD;
        int hi = l & 1, ho = (l + 1) & 1;
        int writef = (l < LL - 1) ? 1 : 0;

        // fork after k_agg(l-1): hs GEMM overlaps with fni/fnj GEMM + edge kernel
        cudaEventRecord(evF, s0);
        cudaStreamWaitEvent(sB, evF, 0);
        k_mmhs<<<NN / 128, 256, SMEM_T3, sB>>>(hph[hi], hpl[hi], l, hs);
        cudaEventRecord(evJ, sB);

        k_mm2h<<<g2, 256, SMEM_T1>>>(hph[hi], l, fni16, fnj16);
        k_edge<<<EE / 128, 256, SMEM_T1>>>(eph[hi], l, bias_l, attn_l,
                                           eph[ho], fni16, fnj16, writef);

        // join before aggregation (needs hs)
        cudaStreamWaitEvent(s0, evJ, 0);
        k_agg<<<NN / 4, 256>>>(hs, hph[ho], hpl[ho]);
    }

    k_mmbr<<<NN / 128, 256, SMEM_T3>>>(hph[0], hpl[0], hfin, bf);
    k_sort<<<(NN * 32 + 255) / 256, 256>>>(hfin, hsort);
    k_topk<<<BB / 4, 128>>>();
    k_ft<<<BB, 128>>>(W3, al3, ar3, hsort);
    k_fg<<<(BB * 32 + 255) / 256, 256>>>(fg_src, fg_dst, b3);
    k_final<<<BB, 128>>>(Wl, bl, Wc, bc, out);
}

// round 16
// speedup vs baseline: 1.5583x; 1.0679x over previous
#include <cuda_runtime.h>
#include <cuda_fp16.h>

#define DD 128
#define NN 25600
#define EE 409600
#define BB 128
#define EFE 1024
#define LL 8
#define KK 32
#define NPG 200

// ---------------- scratch (device globals; allocation-free rule) ----------------
__device__ __align__(256) unsigned g_eph0[EE * 64];
__device__ __align__(256) unsigned g_eph1[EE * 64];
__device__ __align__(256) unsigned g_hph0[NN * 64];
__device__ __align__(256) unsigned g_hpl0[NN * 64];
__device__ __align__(256) unsigned g_hph1[NN * 64];
__device__ __align__(256) unsigned g_hpl1[NN * 64];
__device__ __align__(256) unsigned g_fni16[NN * 64];
__device__ __align__(256) unsigned g_fnj16[NN * 64];
__device__ __align__(256) float g_hs[NN * DD];
__device__ __align__(256) float g_hfin[NN * DD];
__device__ __align__(256) float g_hsort[NN * DD];
__device__ __align__(256) float g_score[EE];
__device__ __align__(256) float g_lastch[NN];
__device__ __align__(256) int   g_topk[BB * KK];
__device__ __align__(256) float g_ft[BB * DD];
__device__ __align__(256) float g_sl[BB];
__device__ __align__(256) float g_sr[BB];
__device__ __align__(256) float g_gv[BB * DD];
__device__ __align__(256) float g_embW[100 * DD];
__device__ __align__(256) int   g_cursor[NN];
__device__ __align__(256) int   g_rowstart[NN + 1];
__device__ __align__(256) int   g_perm[EE];
__device__ __align__(256) int   g_psrc[EE];
__device__ __align__(256) int   g_pdst[EE];
__device__ __align__(256) int   g_ptoke[EE];
__device__ __align__(256) unsigned g_wpkh[33 * 8192];
__device__ __align__(256) unsigned g_wpkl[33 * 8192];

// ---------------- helpers ----------------
__device__ __forceinline__ unsigned packsplit(float x0, float x1, unsigned& lo) {
    __half h0 = __float2half_rn(x0), h1 = __float2half_rn(x1);
    __half l0 = __float2half_rn(x0 - __half2float(h0));
    __half l1 = __float2half_rn(x1 - __half2float(h1));
    lo = ((unsigned)__half_as_ushort(l1) << 16) | (unsigned)__half_as_ushort(l0);
    return ((unsigned)__half_as_ushort(h1) << 16) | (unsigned)__half_as_ushort(h0);
}
__device__ __forceinline__ unsigned pack2(float x0, float x1) {
    __half2 h2 = __floats2half2_rn(x0, x1);
    return reinterpret_cast<unsigned&>(h2);
}
__device__ __forceinline__ float2 unpack2(unsigned u) {
    return __half22float2(reinterpret_cast<__half2&>(u));
}
__device__ __forceinline__ void mma16(float c[4], const unsigned a[4], const unsigned b[2]) {
    asm volatile(
        "mma.sync.aligned.m16n8k16.row.col.f32.f16.f16.f32 "
        "{%0,%1,%2,%3},{%4,%5,%6,%7},{%8,%9},{%0,%1,%2,%3};"
        : "+f"(c[0]), "+f"(c[1]), "+f"(c[2]), "+f"(c[3])
        : "r"(a[0]), "r"(a[1]), "r"(a[2]), "r"(a[3]), "r"(b[0]), "r"(b[1]));
}
__device__ __forceinline__ void ldsm4(unsigned r[4], unsigned addr) {
    asm volatile("ldmatrix.sync.aligned.m8n8.x4.shared.b16 {%0,%1,%2,%3}, [%4];"
        : "=r"(r[0]), "=r"(r[1]), "=r"(r[2]), "=r"(r[3]) : "r"(addr));
}
__device__ __forceinline__ void cpasync16(unsigned saddr, const void* g) {
    asm volatile("cp.async.ca.shared.global [%0], [%1], 16;" :: "r"(saddr), "l"(g));
}

// ---------------- CSR build + edge permutation ----------------
__global__ void k_zero_cursor() {
    int i = blockIdx.x * blockDim.x + threadIdx.x;
    if (i < NN) g_cursor[i] = 0;
}
__global__ void k_count(const int* __restrict__ dst) {
    int e = blockIdx.x * blockDim.x + threadIdx.x;
    if (e < EE) atomicAdd(&g_cursor[dst[e]], 1);
}
__global__ void k_scan() {
    __shared__ int s[1024];
    __shared__ int carry;
    int tid = threadIdx.x;
    if (tid == 0) carry = 0;
    __syncthreads();
    for (int base = 0; base < NN; base += 1024) {
        int i = base + tid;
        int v = (i < NN) ? g_cursor[i] : 0;
        s[tid] = v;
        __syncthreads();
        for (int off = 1; off < 1024; off <<= 1) {
            int t = (tid >= off) ? s[tid - off] : 0;
            __syncthreads();
            s[tid] += t;
            __syncthreads();
        }
        int excl = s[tid] - v;
        int bc = carry;
        if (i < NN) g_rowstart[i] = bc + excl;
        __syncthreads();
        if (tid == 0) carry = bc + s[1023];
        __syncthreads();
    }
    if (tid == 0) g_rowstart[NN] = carry;
}
__global__ void k_copy_cursor() {
    int i = blockIdx.x * blockDim.x + threadIdx.x;
    if (i < NN) g_cursor[i] = g_rowstart[i];
}
__global__ void k_scatter(const int* __restrict__ dst) {
    int e = blockIdx.x * blockDim.x + threadIdx.x;
    if (e < EE) {
        int p = atomicAdd(&g_cursor[dst[e]], 1);
        g_perm[p] = e;
    }
}
__global__ void k_permute(const int* __restrict__ src, const int* __restrict__ dst,
                          const int* __restrict__ toke) {
    int p = blockIdx.x * blockDim.x + threadIdx.x;
    if (p < EE) {
        int e = g_perm[p];
        g_psrc[p] = src[e];
        g_pdst[p] = dst[e];
        g_ptoke[p] = toke[e];
    }
}

// ---------------- init: h = relu(token_emb[tokens_h]) -> packed ----------------
__global__ void k_hinit(const int* __restrict__ tok, const float* __restrict__ emb) {
    int i = blockIdx.x * blockDim.x + threadIdx.x;
    if (i >= NN * 32) return;
    int n = i >> 5, c4 = i & 31;
    float4 v = ((const float4*)emb)[tok[n] * 32 + c4];
    v.x = fmaxf(v.x, 0.f); v.y = fmaxf(v.y, 0.f);
    v.z = fmaxf(v.z, 0.f); v.w = fmaxf(v.w, 0.f);
    unsigned lo0, lo1;
    unsigned hi0 = packsplit(v.x, v.y, lo0);
    unsigned hi1 = packsplit(v.z, v.w, lo1);
    ((uint2*)g_hph0)[n * 32 + c4] = make_uint2(hi0, hi1);
    ((uint2*)g_hpl0)[n * 32 + c4] = make_uint2(lo0, lo1);
}

__global__ void k_embw(const float* __restrict__ etok, const float* __restrict__ W) {
    int t = blockIdx.x, n = threadIdx.x;
    float acc = 0.f;
    #pragma unroll 8
    for (int k = 0; k < DD; k++) acc += etok[t * DD + k] * W[k * DD + n];
    g_embW[t * DD + n] = acc;
}

// ---------------- weight pre-pack ----------------
__global__ void k_wpack(const float* __restrict__ Wni, const float* __restrict__ Wnj,
                        const float* __restrict__ Wno, const float* __restrict__ Wfij,
                        const float* __restrict__ Wf) {
    extern __shared__ float sw[];
    int m = blockIdx.x, tid = threadIdx.x;
    const float* W = (m < 8) ? Wni + m * 16384
                   : (m < 16) ? Wnj + (m - 8) * 16384
                   : (m < 24) ? Wno + (m - 16) * 16384
                   : (m < 32) ? Wfij + (m - 24) * 16384
                   : Wf;
    for (int i = tid; i < 16384; i += 256) {
        int k = i >> 7, n = i & 127;
        sw[n * 129 + k] = W[i];
    }
    __syncthreads();
    int n = tid >> 1, ko = (tid & 1) * 64;
    #pragma unroll 8
    for (int p = 0; p < 32; p++) {
        int k = ko + 2 * p;
        float f0 = sw[n * 129 + k], f1 = sw[n * 129 + k + 1];
        unsigned lo;
        unsigned hi = packsplit(f0, f1, lo);
        g_wpkh[m * 8192 + n * 64 + (ko >> 1) + p] = hi;
        g_wpkl[m * 8192 + n * 64 + (ko >> 1) + p] = lo;
    }
}

// ================= split-fp16 tensor-core GEMM core =================
#define PADH 20
#define SMEM_T3 ((2 * 10240 + 128) * 4)
#define SMEM_T1 ((2 * 5120 + 128) * 4)

extern __shared__ unsigned smem_u[];

template <int TERMS>
__device__ __forceinline__ void mma_tile_t(const unsigned* __restrict__ AH,
                                           const unsigned* __restrict__ AL,
                                           const unsigned* __restrict__ WH,
                                           const unsigned* __restrict__ WL,
                                           int m0, float acc[2][8][4],
                                           int tid, int lane, int warp_m, int warp_n) {
    constexpr bool SPLITA = (TERMS == 3);
    constexpr bool WLO = (TERMS >= 2);
    constexpr unsigned OAL = 2560u;
    constexpr unsigned OWH = SPLITA ? 5120u : 2560u;
    constexpr unsigned OWL = OWH + 2560u;
    constexpr unsigned BUF = 2560u * (2 + (SPLITA ? 1 : 0) + (WLO ? 1 : 0));
    unsigned sb = (unsigned)__cvta_generic_to_shared(smem_u);
    int row_in = lane & 7, grp = lane >> 3;
    unsigned aHaddr[2], aLaddr[2];
    #pragma unroll
    for (int mf = 0; mf < 2; mf++) {
        int r = warp_m * 32 + mf * 16 + (grp & 1) * 8 + row_in;
        int p = (grp >> 1) * 4;
        aHaddr[mf] = sb + (r * PADH + p) * 4;
        if (SPLITA) aLaddr[mf] = sb + (OAL + r * PADH + p) * 4;
    }
    unsigned bHaddr[4], bLaddr[4];
    #pragma unroll
    for (int q = 0; q < 4; q++) {
        int n = warp_n * 64 + (2 * q + (grp >> 1)) * 8 + row_in;
        int p = (grp & 1) * 4;
        bHaddr[q] = sb + (OWH + n * PADH + p) * 4;
        if (WLO) bLaddr[q] = sb + (OWL + n * PADH + p) * 4;
    }
    int r0 = tid >> 2, c0 = tid & 3;
    int r1 = r0 + 64;

    #define COPY_CHUNK(kc, b) do {                                                   \
        unsigned base = sb + (b) * (BUF * 4);                                        \
        unsigned d0 = (r0 * PADH + c0 * 4) * 4, d1 = (r1 * PADH + c0 * 4) * 4;       \
        size_t ga0 = (size_t)(m0 + r0) * 64 + (kc) * 16 + c0 * 4;                    \
        size_t ga1 = (size_t)(m0 + r1) * 64 + (kc) * 16 + c0 * 4;                    \
        size_t gw0 = (size_t)r0 * 64 + (kc) * 16 + c0 * 4;                           \
        size_t gw1 = (size_t)r1 * 64 + (kc) * 16 + c0 * 4;                           \
        cpasync16(base + d0, AH + ga0);                                              \
        cpasync16(base + d1, AH + ga1);                                              \
        if (SPLITA) {                                                                \
            cpasync16(base + OAL * 4 + d0, AL + ga0);                                \
            cpasync16(base + OAL * 4 + d1, AL + ga1);                                \
        }                                                                            \
        cpasync16(base + OWH * 4 + d0, WH + gw0);                                    \
        cpasync16(base + OWH * 4 + d1, WH + gw1);                                    \
        if (WLO) {                                                                   \
            cpasync16(base + OWL * 4 + d0, WL + gw0);                                \
            cpasync16(base + OWL * 4 + d1, WL + gw1);                                \
        }                                                                            \
        asm volatile("cp.async.commit_group;");                                      \
    } while (0)

    COPY_CHUNK(0, 0);
    #pragma unroll
    for (int kc = 0; kc < 4; kc++) {
        if (kc < 3) {
            COPY_CHUNK(kc + 1, (kc + 1) & 1);
            asm volatile("cp.async.wait_group 1;");
        } else {
            asm volatile("cp.async.wait_group 0;");
        }
        __syncthreads();
        unsigned boff = (kc & 1) * (BUF * 4);
        #pragma unroll
        for (int s = 0; s < 2; s++) {
            unsigned soff = boff + s * 32;
            unsigned ah[2][4], al[2][4];
            ldsm4(ah[0], aHaddr[0] + soff);
            ldsm4(ah[1], aHaddr[1] + soff);
            if (SPLITA) {
                ldsm4(al[0], aLaddr[0] + soff);
                ldsm4(al[1], aLaddr[1] + soff);
            }
            #pragma unroll
            for (int q = 0; q < 4; q++) {
                unsigned bh[4], bl[4];
                ldsm4(bh, bHaddr[q] + soff);
                if (WLO) ldsm4(bl, bLaddr[q] + soff);
                #pragma unroll
                for (int mf = 0; mf < 2; mf++) {
                    mma16(acc[mf][2 * q], ah[mf], bh);
                    if (WLO) mma16(acc[mf][2 * q], ah[mf], bl);
                    if (SPLITA) mma16(acc[mf][2 * q], al[mf], bh);
                    mma16(acc[mf][2 * q + 1], ah[mf], bh + 2);
                    if (WLO) mma16(acc[mf][2 * q + 1], ah[mf], bl + 2);
                    if (SPLITA) mma16(acc[mf][2 * q + 1], al[mf], bh + 2);
                }
            }
        }
        __syncthreads();
    }
    #undef COPY_CHUNK
}

// --- fni/fnj GEMMs (1-term; outputs rounded to fp16 anyway) ---
__global__ void __launch_bounds__(256, 2) k_mm2h(const unsigned* __restrict__ AH, int l,
                                                 unsigned* __restrict__ C0h,
                                                 unsigned* __restrict__ C1h) {
    int by = blockIdx.y;
    int m = by * 8 + l;
    int tid = threadIdx.x, lane = tid & 31, w = tid >> 5;
    int warp_m = w >> 1, warp_n = w & 1;
    int m0 = blockIdx.x * 128;
    float acc[2][8][4];
    #pragma unroll
    for (int mf = 0; mf < 2; mf++)
        #pragma unroll
        for (int nf = 0; nf < 8; nf++)
            #pragma unroll
            for (int r = 0; r < 4; r++) acc[mf][nf][r] = 0.f;
    mma_tile_t<1>(AH, nullptr, g_wpkh + m * 8192, nullptr, m0, acc, tid, lane, warp_m, warp_n);
    unsigned* Ch = (by == 0) ? C0h : C1h;
    #pragma unroll
    for (int mf = 0; mf < 2; mf++) {
        int rbase = m0 + warp_m * 32 + mf * 16 + (lane >> 2);
        #pragma unroll
        for (int nf = 0; nf < 8; nf++) {
            int col = warp_n * 64 + nf * 8 + 2 * (lane & 3);
            Ch[(size_t)rbase * 64 + (col >> 1)] = pack2(acc[mf][nf][0], acc[mf][nf][1]);
            Ch[(size_t)(rbase + 8) * 64 + (col >> 1)] = pack2(acc[mf][nf][2], acc[mf][nf][3]);
        }
    }
}

// --- hs GEMM (3-term exact; h-chain precision) ---
__global__ void __launch_bounds__(256, 2) k_mmhs(const unsigned* __restrict__ AH,
                                                 const unsigned* __restrict__ AL, int l,
                                                 float* __restrict__ C2) {
    int m = 16 + l;
    int tid = threadIdx.x, lane = tid & 31, w = tid >> 5;
    int warp_m = w >> 1, warp_n = w & 1;
    int m0 = blockIdx.x * 128;
    float acc[2][8][4];
    #pragma unroll
    for (int mf = 0; mf < 2; mf++)
        #pragma unroll
        for (int nf = 0; nf < 8; nf++)
            #pragma unroll
            for (int r = 0; r < 4; r++) acc[mf][nf][r] = 0.f;
    mma_tile_t<3>(AH, AL, g_wpkh + m * 8192, g_wpkl + m * 8192, m0, acc, tid, lane, warp_m, warp_n);
    #pragma unroll
    for (int mf = 0; mf < 2; mf++) {
        int rbase = m0 + warp_m * 32 + mf * 16 + (lane >> 2);
        #pragma unroll
        for (int nf = 0; nf < 8; nf++) {
            int col = warp_n * 64 + nf * 8 + 2 * (lane & 3);
            *(float2*)&C2[(size_t)rbase * 128 + col] = make_float2(acc[mf][nf][0], acc[mf][nf][1]);
            *(float2*)&C2[(size_t)(rbase + 8) * 128 + col] = make_float2(acc[mf][nf][2], acc[mf][nf][3]);
        }
    }
}

// --- single GEMM with bias + relu (final Wf, 3-term exact) ---
__global__ void __launch_bounds__(256, 2) k_mmbr(const unsigned* __restrict__ AH,
                                                 const unsigned* __restrict__ AL,
                                                 float* __restrict__ C,
                                                 const float* __restrict__ bias) {
    int tid = threadIdx.x, lane = tid & 31, w = tid >> 5;
    int warp_m = w >> 1, warp_n = w & 1;
    int m0 = blockIdx.x * 128;
    float acc[2][8][4];
    #pragma unroll
    for (int mf = 0; mf < 2; mf++)
        #pragma unroll
        for (int nf = 0; nf < 8; nf++)
            #pragma unroll
            for (int r = 0; r < 4; r++) acc[mf][nf][r] = 0.f;
    mma_tile_t<3>(AH, AL, g_wpkh + 32 * 8192, g_wpkl + 32 * 8192, m0, acc, tid, lane, warp_m, warp_n);
    #pragma unroll
    for (int mf = 0; mf < 2; mf++) {
        int rbase = m0 + warp_m * 32 + mf * 16 + (lane >> 2);
        #pragma unroll
        for (int nf = 0; nf < 8; nf++) {
            int col = warp_n * 64 + nf * 8 + 2 * (lane & 3);
            float b0 = __ldg(&bias[col]), b1 = __ldg(&bias[col + 1]);
            float2 lo = make_float2(fmaxf(acc[mf][nf][0] + b0, 0.f), fmaxf(acc[mf][nf][1] + b1, 0.f));
            float2 hi = make_float2(fmaxf(acc[mf][nf][2] + b0, 0.f), fmaxf(acc[mf][nf][3] + b1, 0.f));
            *(float2*)&C[(size_t)rbase * 128 + col] = lo;
            *(float2*)&C[(size_t)(rbase + 8) * 128 + col] = hi;
        }
    }
}

// --- fused edge kernel (layers 1..7): 1-term GEMM + gathers + leaky + attn-dot ---
__global__ void __launch_bounds__(256, 2) k_edge(const unsigned* __restrict__ EH, int l,
                                                 const float* __restrict__ bias,
                                                 const float* __restrict__ attn,
                                                 unsigned* __restrict__ FoutH,
                                                 const unsigned* __restrict__ fni16,
                                                 const unsigned* __restrict__ fnj16,
                                                 int writef) {
    float* ssc = (float*)(smem_u + 2 * 5120);
    int tid = threadIdx.x, lane = tid & 31, w = tid >> 5;
    int warp_m = w >> 1, warp_n = w & 1;
    int m0 = blockIdx.x * 128;
    if (tid < 128) ssc[tid] = 0.f;
    float acc[2][8][4];
    #pragma unroll
    for (int mf = 0; mf < 2; mf++)
        #pragma unroll
        for (int nf = 0; nf < 8; nf++)
            #pragma unroll
            for (int r = 0; r < 4; r++) acc[mf][nf][r] = 0.f;
    mma_tile_t<1>(EH, nullptr, g_wpkh + (24 + l) * 8192, nullptr,
                  m0, acc, tid, lane, warp_m, warp_n);

    float bia[8][2], att[8][2];
    #pragma unroll
    for (int nf = 0; nf < 8; nf++) {
        int col = warp_n * 64 + nf * 8 + 2 * (lane & 3);
        bia[nf][0] = __ldg(&bias[col]); bia[nf][1] = __ldg(&bias[col + 1]);
        att[nf][0] = __ldg(&attn[col]); att[nf][1] = __ldg(&attn[col + 1]);
    }

    #pragma unroll
    for (int mf = 0; mf < 2; mf++) {
        #pragma unroll
        for (int h = 0; h < 2; h++) {
            int rloc = warp_m * 32 + mf * 16 + (lane >> 2) + 8 * h;
            int e = m0 + rloc;
            int s = g_psrc[e], dt = g_pdst[e];
            const unsigned* fr = fni16 + (size_t)s * 64;
            const unsigned* gr = fnj16 + (size_t)dt * 64;
            float part = 0.f;
            #pragma unroll
            for (int nf = 0; nf < 8; nf++) {
                int col = warp_n * 64 + nf * 8 + 2 * (lane & 3);
                float2 fv = unpack2(__ldg(&fr[col >> 1]));
                float2 gv = unpack2(__ldg(&gr[col >> 1]));
                float v0 = acc[mf][nf][2 * h + 0] + fv.x + gv.x + bia[nf][0];
                float v1 = acc[mf][nf][2 * h + 1] + fv.y + gv.y + bia[nf][1];
                v0 = (v0 >= 0.f) ? v0 : 0.01f * v0;
                v1 = (v1 >= 0.f) ? v1 : 0.01f * v1;
                if (writef)
                    FoutH[(size_t)e * 64 + (col >> 1)] = pack2(v0, v1);
                part += v0 * att[nf][0] + v1 * att[nf][1];
            }
            part += __shfl_xor_sync(0xffffffffu, part, 1);
            part += __shfl_xor_sync(0xffffffffu, part, 2);
            if ((lane & 3) == 0) atomicAdd(&ssc[rloc], part);
        }
    }
    __syncthreads();
    if (tid < 128) g_score[m0 + tid] = ssc[tid];
}

// layer-0 edge kernel (permuted): gather table; fp16 fni/fnj
__global__ void k_edge_l0(const float* __restrict__ bias,
                          const float* __restrict__ attn,
                          unsigned* __restrict__ FoutH,
                          const unsigned* __restrict__ fni16,
                          const unsigned* __restrict__ fnj16) {
    int w = (blockIdx.x * blockDim.x + threadIdx.x) >> 5;
    int lane = threadIdx.x & 31;
    if (w >= EE) return;
    int te = g_ptoke[w], s = g_psrc[w], dt = g_pdst[w];
    float4 a = ((const float4*)g_embW)[te * 32 + lane];
    uint2 bu = ((const uint2*)(fni16 + (size_t)s * 64))[lane];
    uint2 cu = ((const uint2*)(fnj16 + (size_t)dt * 64))[lane];
    float2 b01 = unpack2(bu.x), b23 = unpack2(bu.y);
    float2 c01 = unpack2(cu.x), c23 = unpack2(cu.y);
    float4 bi = ((const float4*)bias)[lane];
    float4 at = ((const float4*)attn)[lane];
    float4 v;
    v.x = a.x + b01.x + c01.x + bi.x; v.x = (v.x >= 0.f) ? v.x : 0.01f * v.x;
    v.y = a.y + b01.y + c01.y + bi.y; v.y = (v.y >= 0.f) ? v.y : 0.01f * v.y;
    v.z = a.z + b23.x + c23.x + bi.z; v.z = (v.z >= 0.f) ? v.z : 0.01f * v.z;
    v.w = a.w + b23.y + c23.y + bi.w; v.w = (v.w >= 0.f) ? v.w : 0.01f * v.w;
    ((uint2*)FoutH)[(size_t)w * 32 + lane] = make_uint2(pack2(v.x, v.y), pack2(v.z, v.w));
    float part = v.x * at.x + v.y * at.y + v.z * at.z + v.w * at.w;
    #pragma unroll
    for (int off = 16; off; off >>= 1)
        part += __shfl_xor_sync(0xffffffffu, part, off);
    if (lane == 0) g_score[w] = part;
}

// ---------------- fused edge-softmax + aggregation + relu (1 warp/node, lane-parallel exp) ----
__global__ void k_agg(const float* __restrict__ hsrc,
                      unsigned* __restrict__ HoutH, unsigned* __restrict__ HoutL) {
    int w = (blockIdx.x * blockDim.x + threadIdx.x) >> 5;
    int lane = threadIdx.x & 31;
    if (w >= NN) return;
    int beg = g_rowstart[w], end = g_rowstart[w + 1];
    float mx = -3.4e38f;
    for (int i = beg + lane; i < end; i += 32)
        mx = fmaxf(mx, g_score[i]);
    #pragma unroll
    for (int off = 16; off; off >>= 1)
        mx = fmaxf(mx, __shfl_xor_sync(0xffffffffu, mx, off));
    float s = 0.f;
    float4 acc = make_float4(0.f, 0.f, 0.f, 0.f);
    for (int cb = beg; cb < end; cb += 64) {
        int cend = min(cb + 64, end);
        float ex0 = (cb + lane < cend) ? expf(g_score[cb + lane] - mx) : 0.f;
        float ex1 = (cb + 32 + lane < cend) ? expf(g_score[cb + 32 + lane] - mx) : 0.f;
        for (int i = cb; i < cend; i++) {
            int r = i - cb;
            float ex = __shfl_sync(0xffffffffu, (r < 32) ? ex0 : ex1, r & 31);
            s += ex;
            float4 hv = ((const float4*)hsrc)[g_psrc[i] * 32 + lane];
            acc.x += ex * hv.x; acc.y += ex * hv.y;
            acc.z += ex * hv.z; acc.w += ex * hv.w;
        }
    }
    if (s > 0.f) {
        float inv = 1.0f / s;
        acc.x *= inv; acc.y *= inv; acc.z *= inv; acc.w *= inv;
    }
    acc.x = fmaxf(acc.x, 0.f); acc.y = fmaxf(acc.y, 0.f);
    acc.z = fmaxf(acc.z, 0.f); acc.w = fmaxf(acc.w, 0.f);
    unsigned lo0, lo1;
    unsigned hi0 = packsplit(acc.x, acc.y, lo0);
    unsigned hi1 = packsplit(acc.z, acc.w, lo1);
    ((uint2*)HoutH)[w * 32 + lane] = make_uint2(hi0, hi1);
    ((uint2*)HoutL)[w * 32 + lane] = make_uint2(lo0, lo1);
}

// ---------------- per-node bitonic sort of 128 features ----------------
__global__ void k_sort(const float* __restrict__ Hin, float* __restrict__ Hsort) {
    int w = (blockIdx.x * blockDim.x + threadIdx.x) >> 5;
    int lane = threadIdx.x & 31;
    if (w >= NN) return;
    float v[4];
    #pragma unroll
    for (int r = 0; r < 4; r++) v[r] = Hin[w * 128 + r * 32 + lane];
    for (int k = 2; k <= 128; k <<= 1) {
        for (int j = k >> 1; j; j >>= 1) {
            if (j < 32) {
                #pragma unroll
                for (int r = 0; r < 4; r++) {
                    int idx = r * 32 + lane;
                    float o = __shfl_xor_sync(0xffffffffu, v[r], j);
                    bool up = ((idx & k) == 0);
                    bool lower = ((idx & j) == 0);
                    v[r] = (lower == up) ? fminf(v[r], o) : fmaxf(v[r], o);
                }
            } else {
                int jr = j >> 5;
                #pragma unroll
                for (int r = 0; r < 4; r++) {
                    if ((r & jr) == 0) {
                        int r2 = r | jr;
                        bool up = (((r * 32) & k) == 0);
                        float a = v[r], b = v[r2];
                        float lo = fminf(a, b), hi = fmaxf(a, b);
                        v[r] = up ? lo : hi;
                        v[r2] = up ? hi : lo;
                    }
                }
            }
        }
    }
    #pragma unroll
    for (int r = 0; r < 4; r++) Hsort[w * 128 + r * 32 + lane] = v[r];
    float last = __shfl_sync(0xffffffffu, v[3], 31);
    if (lane == 0) g_lastch[w] = last;
}

// ---------------- top-32 nodes per graph ----------------
__global__ void k_topk() {
    __shared__ float cand[4][NPG];
    int wp = threadIdx.x >> 5, lane = threadIdx.x & 31;
    int b = blockIdx.x * 4 + wp;
    float* cn = cand[wp];
    for (int i = lane; i < NPG; i += 32) cn[i] = g_lastch[b * NPG + i];
    __syncwarp();
    for (int kk = 0; kk < KK; kk++) {
        float bv = -3.4e38f;
        int bi = 1 << 30;
        for (int i = lane; i < NPG; i += 32) {
            float v = cn[i];
            if (v > bv || (v == bv && i < bi)) { bv = v; bi = i; }
        }
        #pragma unroll
        for (int off = 16; off; off >>= 1) {
            float ov = __shfl_xor_sync(0xffffffffu, bv, off);
            int oi = __shfl_xor_sync(0xffffffffu, bi, off);
            if (ov > bv || (ov == bv && oi < bi)) { bv = ov; bi = oi; }
        }
        if (lane == 0) {
            g_topk[b * KK + kk] = b * NPG + bi;
            cn[bi] = -3.4e38f;
        }
        __syncwarp();
    }
}

// ---------------- ft = pooled @ W3; sl/sr (4 independent accumulators) ----------------
__global__ void k_ft(const float* __restrict__ W3, const float* __restrict__ al,
                     const float* __restrict__ ar, const float* __restrict__ Hsort) {
    __shared__ float pool[KK * DD];
    __shared__ float red[DD];
    int b = blockIdx.x, n = threadIdx.x;
    for (int kk = 0; kk < KK; kk++) {
        int node = g_topk[b * KK + kk];
        pool[kk * DD + n] = Hsort[node * DD + n];
    }
    __syncthreads();
    float a0 = 0.f, a1 = 0.f, a2 = 0.f, a3 = 0.f;
    #pragma unroll 4
    for (int i = 0; i < KK * DD; i += 4) {
        a0 += pool[i] * W3[(size_t)i * DD + n];
        a1 += pool[i + 1] * W3[(size_t)(i + 1) * DD + n];
        a2 += pool[i + 2] * W3[(size_t)(i + 2) * DD + n];
        a3 += pool[i + 3] * W3[(size_t)(i + 3) * DD + n];
    }
    float acc = (a0 + a1) + (a2 + a3);
    g_ft[b * DD + n] = acc;
    red[n] = acc * al[n];
    __syncthreads();
    for (int s = 64; s; s >>= 1) { if (n < s) red[n] += red[n + s]; __syncthreads(); }
    if (n == 0) g_sl[b] = red[0];
    __syncthreads();
    red[n] = acc * ar[n];
    __syncthreads();
    for (int s = 64; s; s >>= 1) { if (n < s) red[n] += red[n + s]; __syncthreads(); }
    if (n == 0) g_sr[b] = red[0];
}

// ---------------- graph-level GAT ----------------
__global__ void k_fg(const int* __restrict__ fgs, const int* __restrict__ fgd,
                     const float* __restrict__ b3) {
    int w = (blockIdx.x * blockDim.x + threadIdx.x) >> 5;
    int lane = threadIdx.x & 31;
    if (w >= BB) return;
    float srb = g_sr[w];
    float mx = -3.4e38f;
    for (int i = lane; i < EFE; i += 32) {
        if (fgd[i] == w) {
            float s = g_sl[fgs[i]] + srb;
            s = (s >= 0.f) ? s : 0.2f * s;
            mx = fmaxf(mx, s);
        }
    }
    #pragma unroll
    for (int off = 16; off; off >>= 1)
        mx = fmaxf(mx, __shfl_xor_sync(0xffffffffu, mx, off));
    float sm = 0.f;
    for (int i = lane; i < EFE; i += 32) {
        if (fgd[i] == w) {
            float s = g_sl[fgs[i]] + srb;
            s = (s >= 0.f) ? s : 0.2f * s;
            sm += expf(s - mx);
        }
    }
    #pragma unroll
    for (int off = 16; off; off >>= 1)
        sm += __shfl_xor_sync(0xffffffffu, sm, off);
    float4 acc = make_float4(0.f, 0.f, 0.f, 0.f);
    if (sm > 0.f) {
        float inv = 1.0f / sm;
        for (int i = 0; i < EFE; i++) {
            if (fgd[i] != w) continue;
            float s = g_sl[fgs[i]] + srb;
            s = (s >= 0.f) ? s : 0.2f * s;
            float coef = expf(s - mx) * inv;
            float4 f = ((const float4*)g_ft)[fgs[i] * 32 + lane];
            acc.x += coef * f.x; acc.y += coef * f.y;
            acc.z += coef * f.z; acc.w += coef * f.w;
        }
    }
    float4 bb = ((const float4*)b3)[lane];
    acc.x = fmaxf(acc.x + bb.x, 0.f); acc.y = fmaxf(acc.y + bb.y, 0.f);
    acc.z = fmaxf(acc.z + bb.z, 0.f); acc.w = fmaxf(acc.w + bb.w, 0.f);
    ((float4*)g_gv)[w * 32 + lane] = acc;
}

// ---------------- final ----------------
__global__ void k_final(const float* __restrict__ Wl, const float* __restrict__ bl,
                        const float* __restrict__ Wc, const float* __restrict__ bc,
                        float* __restrict__ out) {
    __shared__ float gs[DD];
    __shared__ float r0[DD], r1[DD];
    int b = blockIdx.x, n = threadIdx.x;
    gs[n] = g_gv[b * DD + n];
    __syncthreads();
    float acc = bl[n];
    #pragma unroll 8
    for (int k = 0; k < DD; k++) acc += gs[k] * Wl[k * DD + n];
    acc = fmaxf(acc, 0.f);
    r0[n] = acc * Wc[n * 2];
    r1[n] = acc * Wc[n * 2 + 1];
    __syncthreads();
    for (int s = 64; s; s >>= 1) {
        if (n < s) { r0[n] += r0[n + s]; r1[n] += r1[n + s]; }
        __syncthreads();
    }
    if (n == 0) {
        out[b * 2] = r0[0] + bc[0];
        out[b * 2 + 1] = r1[0] + bc[1];
    }
}

// ---------------- host ----------------
extern "C" void kernel_launch(void* const* d_in, const int* in_sizes, int n_in,
                              void* d_out, int out_size) {
    const int* tokens_h = (const int*)d_in[0];
    const int* tokens_e = (const int*)d_in[1];
    const int* src = (const int*)d_in[2];
    const int* dst = (const int*)d_in[3];
    const int* fg_src = (const int*)d_in[4];
    const int* fg_dst = (const int*)d_in[5];
    const float* token_emb = (const float*)d_in[6];
    const float* e_token_emb = (const float*)d_in[7];
    const float* W_ni = (const float*)d_in[8];
    const float* W_nj = (const float*)d_in[9];
    const float* W_fij = (const float*)d_in[10];
    const float* W_node = (const float*)d_in[11];
    const float* attn_e = (const float*)d_in[12];
    const float* bias_e = (const float*)d_in[13];
    const float* Wf = (const float*)d_in[14];
    const float* bf = (const float*)d_in[15];
    const float* W3 = (const float*)d_in[16];
    const float* al3 = (const float*)d_in[17];
    const float* ar3 = (const float*)d_in[18];
    const float* b3 = (const float*)d_in[19];
    const float* Wl = (const float*)d_in[20];
    const float* bl = (const float*)d_in[21];
    const float* Wc = (const float*)d_in[22];
    const float* bc = (const float*)d_in[23];
    float* out = (float*)d_out;

    unsigned *eph[2], *hph[2], *hpl[2], *fni16, *fnj16;
    float *hs, *hfin, *hsort;
    cudaGetSymbolAddress((void**)&eph[0], g_eph0);
    cudaGetSymbolAddress((void**)&eph[1], g_eph1);
    cudaGetSymbolAddress((void**)&hph[0], g_hph0);
    cudaGetSymbolAddress((void**)&hpl[0], g_hpl0);
    cudaGetSymbolAddress((void**)&hph[1], g_hph1);
    cudaGetSymbolAddress((void**)&hpl[1], g_hpl1);
    cudaGetSymbolAddress((void**)&fni16, g_fni16);
    cudaGetSymbolAddress((void**)&fnj16, g_fnj16);
    cudaGetSymbolAddress((void**)&hs, g_hs);
    cudaGetSymbolAddress((void**)&hfin, g_hfin);
    cudaGetSymbolAddress((void**)&hsort, g_hsort);

    cudaFuncSetAttribute(k_mm2h, cudaFuncAttributeMaxDynamicSharedMemorySize, SMEM_T1);
    cudaFuncSetAttribute(k_mmhs, cudaFuncAttributeMaxDynamicSharedMemorySize, SMEM_T3);
    cudaFuncSetAttribute(k_mmbr, cudaFuncAttributeMaxDynamicSharedMemorySize, SMEM_T3);
    cudaFuncSetAttribute(k_edge, cudaFuncAttributeMaxDynamicSharedMemorySize, SMEM_T1);
    cudaFuncSetAttribute(k_wpack, cudaFuncAttributeMaxDynamicSharedMemorySize, 129 * 128 * 4);

    // side stream + fork/join events (created once; no device memory involved)
    static cudaStream_t sB = nullptr;
    static cudaEvent_t evF = nullptr, evJ = nullptr, evF2 = nullptr, evJ2 = nullptr;
    if (sB == nullptr) {
        cudaStreamCreateWithFlags(&sB, cudaStreamNonBlocking);
        cudaEventCreateWithFlags(&evF, cudaEventDisableTiming);
        cudaEventCreateWithFlags(&evJ, cudaEventDisableTiming);
        cudaEventCreateWithFlags(&evF2, cudaEventDisableTiming);
        cudaEventCreateWithFlags(&evJ2, cudaEventDisableTiming);
    }
    cudaStream_t s0 = (cudaStream_t)0;

    // fork: CSR build + edge permutation on sB (independent of h-path setup)
    cudaEventRecord(evF, s0);
    cudaStreamWaitEvent(sB, evF, 0);
    k_zero_cursor<<<(NN + 255) / 256, 256, 0, sB>>>();
    k_count<<<(EE + 255) / 256, 256, 0, sB>>>(dst);
    k_scan<<<1, 1024, 0, sB>>>();
    k_copy_cursor<<<(NN + 255) / 256, 256, 0, sB>>>();
    k_scatter<<<(EE + 255) / 256, 256, 0, sB>>>(dst);
    k_permute<<<(EE + 255) / 256, 256, 0, sB>>>(src, dst, tokens_e);
    cudaEventRecord(evJ, sB);

    // main stream: h-path setup + layer-0 fni/fnj GEMM
    k_hinit<<<(NN * 32 + 255) / 256, 256>>>(tokens_h, token_emb);
    k_embw<<<100, 128>>>(e_token_emb, W_fij);
    k_wpack<<<33, 256, 129 * 128 * 4>>>(W_ni, W_nj, W_node, W_fij, Wf);

    dim3 g2(NN / 128, 2, 1);
    k_mm2h<<<g2, 256, SMEM_T1>>>(hph[0], 0, fni16, fnj16);

    // layer-0 hs GEMM on side stream (after h-path setup), overlapping k_edge_l0
    cudaEventRecord(evF2, s0);
    cudaStreamWaitEvent(sB, evF2, 0);
    k_mmhs<<<NN / 128, 256, SMEM_T3, sB>>>(hph[0], hpl[0], 0, hs);
    cudaEventRecord(evJ2, sB);

    // join: layer-0 edge kernel needs the permuted edge arrays
    cudaStreamWaitEvent(s0, evJ, 0);
    k_edge_l0<<<(EE * 32 + 255) / 256, 256>>>(bias_e, attn_e, eph[1], fni16, fnj16);
    // join: agg needs hs
    cudaStreamWaitEvent(s0, evJ2, 0);
    k_agg<<<(NN * 32 + 255) / 256, 256>>>(hs, hph[1], hpl[1]);

    for (int l = 1; l < LL; l++) {
        const float* bias_l = bias_e + l * DD;
        const float* attn_l = attn_e + l * DD;
        int hi = l & 1, ho = (l + 1) & 1;
        int writef = (l < LL - 1) ? 1 : 0;

        // fork after k_agg(l-1): hs GEMM overlaps with fni/fnj GEMM + edge kernel
        cudaEventRecord(evF, s0);
        cudaStreamWaitEvent(sB, evF, 0);
        k_mmhs<<<NN / 128, 256, SMEM_T3, sB>>>(hph[hi], hpl[hi], l, hs);
        cudaEventRecord(evJ, sB);

        k_mm2h<<<g2, 256, SMEM_T1>>>(hph[hi], l, fni16, fnj16);
        k_edge<<<EE / 128, 256, SMEM_T1>>>(eph[hi], l, bias_l, attn_l,
                                           eph[ho], fni16, fnj16, writef);

        // join before aggregation (needs hs)
        cudaStreamWaitEvent(s0, evJ, 0);
        k_agg<<<(NN * 32 + 255) / 256, 256>>>(hs, hph[ho], hpl[ho]);
    }

    k_mmbr<<<NN / 128, 256, SMEM_T3>>>(hph[0], hpl[0], hfin, bf);
    k_sort<<<(NN * 32 + 255) / 256, 256>>>(hfin, hsort);
    k_topk<<<BB / 4, 128>>>();
    k_ft<<<BB, 128>>>(W3, al3, ar3, hsort);
    k_fg<<<(BB * 32 + 255) / 256, 256>>>(fg_src, fg_dst, b3);
    k_final<<<BB, 128>>>(Wl, bl, Wc, bc, out);
}

// round 17
// speedup vs baseline: 1.5711x; 1.0082x over previous
#include <cuda_runtime.h>
#include <cuda_fp16.h>

#define DD 128
#define NN 25600
#define EE 409600
#define BB 128
#define EFE 1024
#define LL 8
#define KK 32
#define NPG 200

// ---------------- scratch (device globals; allocation-free rule) ----------------
__device__ __align__(256) unsigned g_eph0[EE * 64];
__device__ __align__(256) unsigned g_eph1[EE * 64];
__device__ __align__(256) unsigned g_hph0[NN * 64];
__device__ __align__(256) unsigned g_hpl0[NN * 64];
__device__ __align__(256) unsigned g_hph1[NN * 64];
__device__ __align__(256) unsigned g_hpl1[NN * 64];
__device__ __align__(256) unsigned g_fni16[NN * 64];
__device__ __align__(256) unsigned g_fnj16[NN * 64];
__device__ __align__(256) unsigned g_hs16[NN * 64];
__device__ __align__(256) float g_hfin[NN * DD];
__device__ __align__(256) float g_hsort[NN * DD];
__device__ __align__(256) float g_score[EE];
__device__ __align__(256) float g_lastch[NN];
__device__ __align__(256) int   g_topk[BB * KK];
__device__ __align__(256) float g_ft[BB * DD];
__device__ __align__(256) float g_sl[BB];
__device__ __align__(256) float g_sr[BB];
__device__ __align__(256) float g_gv[BB * DD];
__device__ __align__(256) float g_embW[100 * DD];
__device__ __align__(256) int   g_cursor[NN];
__device__ __align__(256) int   g_rowstart[NN + 1];
__device__ __align__(256) int   g_perm[EE];
__device__ __align__(256) int   g_psrc[EE];
__device__ __align__(256) int   g_pdst[EE];
__device__ __align__(256) int   g_ptoke[EE];
__device__ __align__(256) unsigned g_wpkh[33 * 8192];
__device__ __align__(256) unsigned g_wpkl[33 * 8192];

// ---------------- helpers ----------------
__device__ __forceinline__ unsigned packsplit(float x0, float x1, unsigned& lo) {
    __half h0 = __float2half_rn(x0), h1 = __float2half_rn(x1);
    __half l0 = __float2half_rn(x0 - __half2float(h0));
    __half l1 = __float2half_rn(x1 - __half2float(h1));
    lo = ((unsigned)__half_as_ushort(l1) << 16) | (unsigned)__half_as_ushort(l0);
    return ((unsigned)__half_as_ushort(h1) << 16) | (unsigned)__half_as_ushort(h0);
}
__device__ __forceinline__ unsigned pack2(float x0, float x1) {
    __half2 h2 = __floats2half2_rn(x0, x1);
    return reinterpret_cast<unsigned&>(h2);
}
__device__ __forceinline__ float2 unpack2(unsigned u) {
    return __half22float2(reinterpret_cast<__half2&>(u));
}
__device__ __forceinline__ void mma16(float c[4], const unsigned a[4], const unsigned b[2]) {
    asm volatile(
        "mma.sync.aligned.m16n8k16.row.col.f32.f16.f16.f32 "
        "{%0,%1,%2,%3},{%4,%5,%6,%7},{%8,%9},{%0,%1,%2,%3};"
        : "+f"(c[0]), "+f"(c[1]), "+f"(c[2]), "+f"(c[3])
        : "r"(a[0]), "r"(a[1]), "r"(a[2]), "r"(a[3]), "r"(b[0]), "r"(b[1]));
}
__device__ __forceinline__ void ldsm4(unsigned r[4], unsigned addr) {
    asm volatile("ldmatrix.sync.aligned.m8n8.x4.shared.b16 {%0,%1,%2,%3}, [%4];"
        : "=r"(r[0]), "=r"(r[1]), "=r"(r[2]), "=r"(r[3]) : "r"(addr));
}
__device__ __forceinline__ void cpasync16(unsigned saddr, const void* g) {
    asm volatile("cp.async.ca.shared.global [%0], [%1], 16;" :: "r"(saddr), "l"(g));
}

// ---------------- CSR build + edge permutation ----------------
__global__ void k_zero_cursor() {
    int i = blockIdx.x * blockDim.x + threadIdx.x;
    if (i < NN) g_cursor[i] = 0;
}
__global__ void k_count(const int* __restrict__ dst) {
    int e = blockIdx.x * blockDim.x + threadIdx.x;
    if (e < EE) atomicAdd(&g_cursor[dst[e]], 1);
}
__global__ void k_scan() {
    __shared__ int s[1024];
    __shared__ int carry;
    int tid = threadIdx.x;
    if (tid == 0) carry = 0;
    __syncthreads();
    for (int base = 0; base < NN; base += 1024) {
        int i = base + tid;
        int v = (i < NN) ? g_cursor[i] : 0;
        s[tid] = v;
        __syncthreads();
        for (int off = 1; off < 1024; off <<= 1) {
            int t = (tid >= off) ? s[tid - off] : 0;
            __syncthreads();
            s[tid] += t;
            __syncthreads();
        }
        int excl = s[tid] - v;
        int bc = carry;
        if (i < NN) g_rowstart[i] = bc + excl;
        __syncthreads();
        if (tid == 0) carry = bc + s[1023];
        __syncthreads();
    }
    if (tid == 0) g_rowstart[NN] = carry;
}
__global__ void k_copy_cursor() {
    int i = blockIdx.x * blockDim.x + threadIdx.x;
    if (i < NN) g_cursor[i] = g_rowstart[i];
}
__global__ void k_scatter(const int* __restrict__ dst) {
    int e = blockIdx.x * blockDim.x + threadIdx.x;
    if (e < EE) {
        int p = atomicAdd(&g_cursor[dst[e]], 1);
        g_perm[p] = e;
    }
}
__global__ void k_permute(const int* __restrict__ src, const int* __restrict__ dst,
                          const int* __restrict__ toke) {
    int p = blockIdx.x * blockDim.x + threadIdx.x;
    if (p < EE) {
        int e = g_perm[p];
        g_psrc[p] = src[e];
        g_pdst[p] = dst[e];
        g_ptoke[p] = toke[e];
    }
}

// ---------------- init: h = relu(token_emb[tokens_h]) -> packed ----------------
__global__ void k_hinit(const int* __restrict__ tok, const float* __restrict__ emb) {
    int i = blockIdx.x * blockDim.x + threadIdx.x;
    if (i >= NN * 32) return;
    int n = i >> 5, c4 = i & 31;
    float4 v = ((const float4*)emb)[tok[n] * 32 + c4];
    v.x = fmaxf(v.x, 0.f); v.y = fmaxf(v.y, 0.f);
    v.z = fmaxf(v.z, 0.f); v.w = fmaxf(v.w, 0.f);
    unsigned lo0, lo1;
    unsigned hi0 = packsplit(v.x, v.y, lo0);
    unsigned hi1 = packsplit(v.z, v.w, lo1);
    ((uint2*)g_hph0)[n * 32 + c4] = make_uint2(hi0, hi1);
    ((uint2*)g_hpl0)[n * 32 + c4] = make_uint2(lo0, lo1);
}

__global__ void k_embw(const float* __restrict__ etok, const float* __restrict__ W) {
    int t = blockIdx.x, n = threadIdx.x;
    float acc = 0.f;
    #pragma unroll 8
    for (int k = 0; k < DD; k++) acc += etok[t * DD + k] * W[k * DD + n];
    g_embW[t * DD + n] = acc;
}

// ---------------- weight pre-pack ----------------
__global__ void k_wpack(const float* __restrict__ Wni, const float* __restrict__ Wnj,
                        const float* __restrict__ Wno, const float* __restrict__ Wfij,
                        const float* __restrict__ Wf) {
    extern __shared__ float sw[];
    int m = blockIdx.x, tid = threadIdx.x;
    const float* W = (m < 8) ? Wni + m * 16384
                   : (m < 16) ? Wnj + (m - 8) * 16384
                   : (m < 24) ? Wno + (m - 16) * 16384
                   : (m < 32) ? Wfij + (m - 24) * 16384
                   : Wf;
    for (int i = tid; i < 16384; i += 256) {
        int k = i >> 7, n = i & 127;
        sw[n * 129 + k] = W[i];
    }
    __syncthreads();
    int n = tid >> 1, ko = (tid & 1) * 64;
    #pragma unroll 8
    for (int p = 0; p < 32; p++) {
        int k = ko + 2 * p;
        float f0 = sw[n * 129 + k], f1 = sw[n * 129 + k + 1];
        unsigned lo;
        unsigned hi = packsplit(f0, f1, lo);
        g_wpkh[m * 8192 + n * 64 + (ko >> 1) + p] = hi;
        g_wpkl[m * 8192 + n * 64 + (ko >> 1) + p] = lo;
    }
}

// ================= split-fp16 tensor-core GEMM core =================
#define PADH 20
#define SMEM_T3 ((2 * 10240 + 128) * 4)
#define SMEM_T1 ((2 * 5120 + 128) * 4)

extern __shared__ unsigned smem_u[];

template <int TERMS>
__device__ __forceinline__ void mma_tile_t(const unsigned* __restrict__ AH,
                                           const unsigned* __restrict__ AL,
                                           const unsigned* __restrict__ WH,
                                           const unsigned* __restrict__ WL,
                                           int m0, float acc[2][8][4],
                                           int tid, int lane, int warp_m, int warp_n) {
    constexpr bool SPLITA = (TERMS == 3);
    constexpr bool WLO = (TERMS >= 2);
    constexpr unsigned OAL = 2560u;
    constexpr unsigned OWH = SPLITA ? 5120u : 2560u;
    constexpr unsigned OWL = OWH + 2560u;
    constexpr unsigned BUF = 2560u * (2 + (SPLITA ? 1 : 0) + (WLO ? 1 : 0));
    unsigned sb = (unsigned)__cvta_generic_to_shared(smem_u);
    int row_in = lane & 7, grp = lane >> 3;
    unsigned aHaddr[2], aLaddr[2];
    #pragma unroll
    for (int mf = 0; mf < 2; mf++) {
        int r = warp_m * 32 + mf * 16 + (grp & 1) * 8 + row_in;
        int p = (grp >> 1) * 4;
        aHaddr[mf] = sb + (r * PADH + p) * 4;
        if (SPLITA) aLaddr[mf] = sb + (OAL + r * PADH + p) * 4;
    }
    unsigned bHaddr[4], bLaddr[4];
    #pragma unroll
    for (int q = 0; q < 4; q++) {
        int n = warp_n * 64 + (2 * q + (grp >> 1)) * 8 + row_in;
        int p = (grp & 1) * 4;
        bHaddr[q] = sb + (OWH + n * PADH + p) * 4;
        if (WLO) bLaddr[q] = sb + (OWL + n * PADH + p) * 4;
    }
    int r0 = tid >> 2, c0 = tid & 3;
    int r1 = r0 + 64;

    #define COPY_CHUNK(kc, b) do {                                                   \
        unsigned base = sb + (b) * (BUF * 4);                                        \
        unsigned d0 = (r0 * PADH + c0 * 4) * 4, d1 = (r1 * PADH + c0 * 4) * 4;       \
        size_t ga0 = (size_t)(m0 + r0) * 64 + (kc) * 16 + c0 * 4;                    \
        size_t ga1 = (size_t)(m0 + r1) * 64 + (kc) * 16 + c0 * 4;                    \
        size_t gw0 = (size_t)r0 * 64 + (kc) * 16 + c0 * 4;                           \
        size_t gw1 = (size_t)r1 * 64 + (kc) * 16 + c0 * 4;                           \
        cpasync16(base + d0, AH + ga0);                                              \
        cpasync16(base + d1, AH + ga1);                                              \
        if (SPLITA) {                                                                \
            cpasync16(base + OAL * 4 + d0, AL + ga0);                                \
            cpasync16(base + OAL * 4 + d1, AL + ga1);                                \
        }                                                                            \
        cpasync16(base + OWH * 4 + d0, WH + gw0);                                    \
        cpasync16(base + OWH * 4 + d1, WH + gw1);                                    \
        if (WLO) {                                                                   \
            cpasync16(base + OWL * 4 + d0, WL + gw0);                                \
            cpasync16(base + OWL * 4 + d1, WL + gw1);                                \
        }                                                                            \
        asm volatile("cp.async.commit_group;");                                      \
    } while (0)

    COPY_CHUNK(0, 0);
    #pragma unroll
    for (int kc = 0; kc < 4; kc++) {
        if (kc < 3) {
            COPY_CHUNK(kc + 1, (kc + 1) & 1);
            asm volatile("cp.async.wait_group 1;");
        } else {
            asm volatile("cp.async.wait_group 0;");
        }
        __syncthreads();
        unsigned boff = (kc & 1) * (BUF * 4);
        #pragma unroll
        for (int s = 0; s < 2; s++) {
            unsigned soff = boff + s * 32;
            unsigned ah[2][4], al[2][4];
            ldsm4(ah[0], aHaddr[0] + soff);
            ldsm4(ah[1], aHaddr[1] + soff);
            if (SPLITA) {
                ldsm4(al[0], aLaddr[0] + soff);
                ldsm4(al[1], aLaddr[1] + soff);
            }
            #pragma unroll
            for (int q = 0; q < 4; q++) {
                unsigned bh[4], bl[4];
                ldsm4(bh, bHaddr[q] + soff);
                if (WLO) ldsm4(bl, bLaddr[q] + soff);
                #pragma unroll
                for (int mf = 0; mf < 2; mf++) {
                    mma16(acc[mf][2 * q], ah[mf], bh);
                    if (WLO) mma16(acc[mf][2 * q], ah[mf], bl);
                    if (SPLITA) mma16(acc[mf][2 * q], al[mf], bh);
                    mma16(acc[mf][2 * q + 1], ah[mf], bh + 2);
                    if (WLO) mma16(acc[mf][2 * q + 1], ah[mf], bl + 2);
                    if (SPLITA) mma16(acc[mf][2 * q + 1], al[mf], bh + 2);
                }
            }
        }
        __syncthreads();
    }
    #undef COPY_CHUNK
}

// --- fni/fnj GEMMs (1-term; outputs rounded to fp16 anyway) ---
__global__ void __launch_bounds__(256, 2) k_mm2h(const unsigned* __restrict__ AH, int l,
                                                 unsigned* __restrict__ C0h,
                                                 unsigned* __restrict__ C1h) {
    int by = blockIdx.y;
    int m = by * 8 + l;
    int tid = threadIdx.x, lane = tid & 31, w = tid >> 5;
    int warp_m = w >> 1, warp_n = w & 1;
    int m0 = blockIdx.x * 128;
    float acc[2][8][4];
    #pragma unroll
    for (int mf = 0; mf < 2; mf++)
        #pragma unroll
        for (int nf = 0; nf < 8; nf++)
            #pragma unroll
            for (int r = 0; r < 4; r++) acc[mf][nf][r] = 0.f;
    mma_tile_t<1>(AH, nullptr, g_wpkh + m * 8192, nullptr, m0, acc, tid, lane, warp_m, warp_n);
    unsigned* Ch = (by == 0) ? C0h : C1h;
    #pragma unroll
    for (int mf = 0; mf < 2; mf++) {
        int rbase = m0 + warp_m * 32 + mf * 16 + (lane >> 2);
        #pragma unroll
        for (int nf = 0; nf < 8; nf++) {
            int col = warp_n * 64 + nf * 8 + 2 * (lane & 3);
            Ch[(size_t)rbase * 64 + (col >> 1)] = pack2(acc[mf][nf][0], acc[mf][nf][1]);
            Ch[(size_t)(rbase + 8) * 64 + (col >> 1)] = pack2(acc[mf][nf][2], acc[mf][nf][3]);
        }
    }
}

// --- hs GEMM (1-term; output packed fp16 — storage rounding dominates) ---
__global__ void __launch_bounds__(256, 2) k_mmhs(const unsigned* __restrict__ AH, int l,
                                                 unsigned* __restrict__ C2h) {
    int m = 16 + l;
    int tid = threadIdx.x, lane = tid & 31, w = tid >> 5;
    int warp_m = w >> 1, warp_n = w & 1;
    int m0 = blockIdx.x * 128;
    float acc[2][8][4];
    #pragma unroll
    for (int mf = 0; mf < 2; mf++)
        #pragma unroll
        for (int nf = 0; nf < 8; nf++)
            #pragma unroll
            for (int r = 0; r < 4; r++) acc[mf][nf][r] = 0.f;
    mma_tile_t<1>(AH, nullptr, g_wpkh + m * 8192, nullptr, m0, acc, tid, lane, warp_m, warp_n);
    #pragma unroll
    for (int mf = 0; mf < 2; mf++) {
        int rbase = m0 + warp_m * 32 + mf * 16 + (lane >> 2);
        #pragma unroll
        for (int nf = 0; nf < 8; nf++) {
            int col = warp_n * 64 + nf * 8 + 2 * (lane & 3);
            C2h[(size_t)rbase * 64 + (col >> 1)] = pack2(acc[mf][nf][0], acc[mf][nf][1]);
            C2h[(size_t)(rbase + 8) * 64 + (col >> 1)] = pack2(acc[mf][nf][2], acc[mf][nf][3]);
        }
    }
}

// --- single GEMM with bias + relu (final Wf, 3-term exact) ---
__global__ void __launch_bounds__(256, 2) k_mmbr(const unsigned* __restrict__ AH,
                                                 const unsigned* __restrict__ AL,
                                                 float* __restrict__ C,
                                                 const float* __restrict__ bias) {
    int tid = threadIdx.x, lane = tid & 31, w = tid >> 5;
    int warp_m = w >> 1, warp_n = w & 1;
    int m0 = blockIdx.x * 128;
    float acc[2][8][4];
    #pragma unroll
    for (int mf = 0; mf < 2; mf++)
        #pragma unroll
        for (int nf = 0; nf < 8; nf++)
            #pragma unroll
            for (int r = 0; r < 4; r++) acc[mf][nf][r] = 0.f;
    mma_tile_t<3>(AH, AL, g_wpkh + 32 * 8192, g_wpkl + 32 * 8192, m0, acc, tid, lane, warp_m, warp_n);
    #pragma unroll
    for (int mf = 0; mf < 2; mf++) {
        int rbase = m0 + warp_m * 32 + mf * 16 + (lane >> 2);
        #pragma unroll
        for (int nf = 0; nf < 8; nf++) {
            int col = warp_n * 64 + nf * 8 + 2 * (lane & 3);
            float b0 = __ldg(&bias[col]), b1 = __ldg(&bias[col + 1]);
            float2 lo = make_float2(fmaxf(acc[mf][nf][0] + b0, 0.f), fmaxf(acc[mf][nf][1] + b1, 0.f));
            float2 hi = make_float2(fmaxf(acc[mf][nf][2] + b0, 0.f), fmaxf(acc[mf][nf][3] + b1, 0.f));
            *(float2*)&C[(size_t)rbase * 128 + col] = lo;
            *(float2*)&C[(size_t)(rbase + 8) * 128 + col] = hi;
        }
    }
}

// --- fused edge kernel (layers 1..7): 1-term GEMM + gathers + leaky + attn-dot ---
__global__ void __launch_bounds__(256, 2) k_edge(const unsigned* __restrict__ EH, int l,
                                                 const float* __restrict__ bias,
                                                 const float* __restrict__ attn,
                                                 unsigned* __restrict__ FoutH,
                                                 const unsigned* __restrict__ fni16,
                                                 const unsigned* __restrict__ fnj16,
                                                 int writef) {
    float* ssc = (float*)(smem_u + 2 * 5120);
    int tid = threadIdx.x, lane = tid & 31, w = tid >> 5;
    int warp_m = w >> 1, warp_n = w & 1;
    int m0 = blockIdx.x * 128;
    if (tid < 128) ssc[tid] = 0.f;
    float acc[2][8][4];
    #pragma unroll
    for (int mf = 0; mf < 2; mf++)
        #pragma unroll
        for (int nf = 0; nf < 8; nf++)
            #pragma unroll
            for (int r = 0; r < 4; r++) acc[mf][nf][r] = 0.f;
    mma_tile_t<1>(EH, nullptr, g_wpkh + (24 + l) * 8192, nullptr,
                  m0, acc, tid, lane, warp_m, warp_n);

    float bia[8][2], att[8][2];
    #pragma unroll
    for (int nf = 0; nf < 8; nf++) {
        int col = warp_n * 64 + nf * 8 + 2 * (lane & 3);
        bia[nf][0] = __ldg(&bias[col]); bia[nf][1] = __ldg(&bias[col + 1]);
        att[nf][0] = __ldg(&attn[col]); att[nf][1] = __ldg(&attn[col + 1]);
    }

    #pragma unroll
    for (int mf = 0; mf < 2; mf++) {
        #pragma unroll
        for (int h = 0; h < 2; h++) {
            int rloc = warp_m * 32 + mf * 16 + (lane >> 2) + 8 * h;
            int e = m0 + rloc;
            int s = g_psrc[e], dt = g_pdst[e];
            const unsigned* fr = fni16 + (size_t)s * 64;
            const unsigned* gr = fnj16 + (size_t)dt * 64;
            float part = 0.f;
            #pragma unroll
            for (int nf = 0; nf < 8; nf++) {
                int col = warp_n * 64 + nf * 8 + 2 * (lane & 3);
                float2 fv = unpack2(__ldg(&fr[col >> 1]));
                float2 gv = unpack2(__ldg(&gr[col >> 1]));
                float v0 = acc[mf][nf][2 * h + 0] + fv.x + gv.x + bia[nf][0];
                float v1 = acc[mf][nf][2 * h + 1] + fv.y + gv.y + bia[nf][1];
                v0 = (v0 >= 0.f) ? v0 : 0.01f * v0;
                v1 = (v1 >= 0.f) ? v1 : 0.01f * v1;
                if (writef)
                    FoutH[(size_t)e * 64 + (col >> 1)] = pack2(v0, v1);
                part += v0 * att[nf][0] + v1 * att[nf][1];
            }
            part += __shfl_xor_sync(0xffffffffu, part, 1);
            part += __shfl_xor_sync(0xffffffffu, part, 2);
            if ((lane & 3) == 0) atomicAdd(&ssc[rloc], part);
        }
    }
    __syncthreads();
    if (tid < 128) g_score[m0 + tid] = ssc[tid];
}

// layer-0 edge kernel (permuted): gather table; fp16 fni/fnj
__global__ void k_edge_l0(const float* __restrict__ bias,
                          const float* __restrict__ attn,
                          unsigned* __restrict__ FoutH,
                          const unsigned* __restrict__ fni16,
                          const unsigned* __restrict__ fnj16) {
    int w = (blockIdx.x * blockDim.x + threadIdx.x) >> 5;
    int lane = threadIdx.x & 31;
    if (w >= EE) return;
    int te = g_ptoke[w], s = g_psrc[w], dt = g_pdst[w];
    float4 a = ((const float4*)g_embW)[te * 32 + lane];
    uint2 bu = ((const uint2*)(fni16 + (size_t)s * 64))[lane];
    uint2 cu = ((const uint2*)(fnj16 + (size_t)dt * 64))[lane];
    float2 b01 = unpack2(bu.x), b23 = unpack2(bu.y);
    float2 c01 = unpack2(cu.x), c23 = unpack2(cu.y);
    float4 bi = ((const float4*)bias)[lane];
    float4 at = ((const float4*)attn)[lane];
    float4 v;
    v.x = a.x + b01.x + c01.x + bi.x; v.x = (v.x >= 0.f) ? v.x : 0.01f * v.x;
    v.y = a.y + b01.y + c01.y + bi.y; v.y = (v.y >= 0.f) ? v.y : 0.01f * v.y;
    v.z = a.z + b23.x + c23.x + bi.z; v.z = (v.z >= 0.f) ? v.z : 0.01f * v.z;
    v.w = a.w + b23.y + c23.y + bi.w; v.w = (v.w >= 0.f) ? v.w : 0.01f * v.w;
    ((uint2*)FoutH)[(size_t)w * 32 + lane] = make_uint2(pack2(v.x, v.y), pack2(v.z, v.w));
    float part = v.x * at.x + v.y * at.y + v.z * at.z + v.w * at.w;
    #pragma unroll
    for (int off = 16; off; off >>= 1)
        part += __shfl_xor_sync(0xffffffffu, part, off);
    if (lane == 0) g_score[w] = part;
}

// ---------------- fused edge-softmax + aggregation + relu (fp16 hs gather) ----------------
__global__ void k_agg(const unsigned* __restrict__ hs16,
                      unsigned* __restrict__ HoutH, unsigned* __restrict__ HoutL) {
    int w = (blockIdx.x * blockDim.x + threadIdx.x) >> 5;
    int lane = threadIdx.x & 31;
    if (w >= NN) return;
    int beg = g_rowstart[w], end = g_rowstart[w + 1];
    float mx = -3.4e38f;
    for (int i = beg + lane; i < end; i += 32)
        mx = fmaxf(mx, g_score[i]);
    #pragma unroll
    for (int off = 16; off; off >>= 1)
        mx = fmaxf(mx, __shfl_xor_sync(0xffffffffu, mx, off));
    float s = 0.f;
    float4 acc = make_float4(0.f, 0.f, 0.f, 0.f);
    for (int cb = beg; cb < end; cb += 64) {
        int cend = min(cb + 64, end);
        float ex0 = (cb + lane < cend) ? expf(g_score[cb + lane] - mx) : 0.f;
        float ex1 = (cb + 32 + lane < cend) ? expf(g_score[cb + 32 + lane] - mx) : 0.f;
        for (int i = cb; i < cend; i++) {
            int r = i - cb;
            float ex = __shfl_sync(0xffffffffu, (r < 32) ? ex0 : ex1, r & 31);
            s += ex;
            uint2 hu = ((const uint2*)(hs16 + (size_t)g_psrc[i] * 64))[lane];
            float2 h01 = unpack2(hu.x), h23 = unpack2(hu.y);
            acc.x += ex * h01.x; acc.y += ex * h01.y;
            acc.z += ex * h23.x; acc.w += ex * h23.y;
        }
    }
    if (s > 0.f) {
        float inv = 1.0f / s;
        acc.x *= inv; acc.y *= inv; acc.z *= inv; acc.w *= inv;
    }
    acc.x = fmaxf(acc.x, 0.f); acc.y = fmaxf(acc.y, 0.f);
    acc.z = fmaxf(acc.z, 0.f); acc.w = fmaxf(acc.w, 0.f);
    unsigned lo0, lo1;
    unsigned hi0 = packsplit(acc.x, acc.y, lo0);
    unsigned hi1 = packsplit(acc.z, acc.w, lo1);
    ((uint2*)HoutH)[w * 32 + lane] = make_uint2(hi0, hi1);
    ((uint2*)HoutL)[w * 32 + lane] = make_uint2(lo0, lo1);
}

// ---------------- per-node bitonic sort of 128 features ----------------
__global__ void k_sort(const float* __restrict__ Hin, float* __restrict__ Hsort) {
    int w = (blockIdx.x * blockDim.x + threadIdx.x) >> 5;
    int lane = threadIdx.x & 31;
    if (w >= NN) return;
    float v[4];
    #pragma unroll
    for (int r = 0; r < 4; r++) v[r] = Hin[w * 128 + r * 32 + lane];
    for (int k = 2; k <= 128; k <<= 1) {
        for (int j = k >> 1; j; j >>= 1) {
            if (j < 32) {
                #pragma unroll
                for (int r = 0; r < 4; r++) {
                    int idx = r * 32 + lane;
                    float o = __shfl_xor_sync(0xffffffffu, v[r], j);
                    bool up = ((idx & k) == 0);
                    bool lower = ((idx & j) == 0);
                    v[r] = (lower == up) ? fminf(v[r], o) : fmaxf(v[r], o);
                }
            } else {
                int jr = j >> 5;
                #pragma unroll
                for (int r = 0; r < 4; r++) {
                    if ((r & jr) == 0) {
                        int r2 = r | jr;
                        bool up = (((r * 32) & k) == 0);
                        float a = v[r], b = v[r2];
                        float lo = fminf(a, b), hi = fmaxf(a, b);
                        v[r] = up ? lo : hi;
                        v[r2] = up ? hi : lo;
                    }
                }
            }
        }
    }
    #pragma unroll
    for (int r = 0; r < 4; r++) Hsort[w * 128 + r * 32 + lane] = v[r];
    float last = __shfl_sync(0xffffffffu, v[3], 31);
    if (lane == 0) g_lastch[w] = last;
}

// ---------------- top-32 nodes per graph ----------------
__global__ void k_topk() {
    __shared__ float cand[4][NPG];
    int wp = threadIdx.x >> 5, lane = threadIdx.x & 31;
    int b = blockIdx.x * 4 + wp;
    float* cn = cand[wp];
    for (int i = lane; i < NPG; i += 32) cn[i] = g_lastch[b * NPG + i];
    __syncwarp();
    for (int kk = 0; kk < KK; kk++) {
        float bv = -3.4e38f;
        int bi = 1 << 30;
        for (int i = lane; i < NPG; i += 32) {
            float v = cn[i];
            if (v > bv || (v == bv && i < bi)) { bv = v; bi = i; }
        }
        #pragma unroll
        for (int off = 16; off; off >>= 1) {
            float ov = __shfl_xor_sync(0xffffffffu, bv, off);
            int oi = __shfl_xor_sync(0xffffffffu, bi, off);
            if (ov > bv || (ov == bv && oi < bi)) { bv = ov; bi = oi; }
        }
        if (lane == 0) {
            g_topk[b * KK + kk] = b * NPG + bi;
            cn[bi] = -3.4e38f;
        }
        __syncwarp();
    }
}

// ---------------- ft = pooled @ W3; sl/sr (4 independent accumulators) ----------------
__global__ void k_ft(const float* __restrict__ W3, const float* __restrict__ al,
                     const float* __restrict__ ar, const float* __restrict__ Hsort) {
    __shared__ float pool[KK * DD];
    __shared__ float red[DD];
    int b = blockIdx.x, n = threadIdx.x;
    for (int kk = 0; kk < KK; kk++) {
        int node = g_topk[b * KK + kk];
        pool[kk * DD + n] = Hsort[node * DD + n];
    }
    __syncthreads();
    float a0 = 0.f, a1 = 0.f, a2 = 0.f, a3 = 0.f;
    #pragma unroll 4
    for (int i = 0; i < KK * DD; i += 4) {
        a0 += pool[i] * W3[(size_t)i * DD + n];
        a1 += pool[i + 1] * W3[(size_t)(i + 1) * DD + n];
        a2 += pool[i + 2] * W3[(size_t)(i + 2) * DD + n];
        a3 += pool[i + 3] * W3[(size_t)(i + 3) * DD + n];
    }
    float acc = (a0 + a1) + (a2 + a3);
    g_ft[b * DD + n] = acc;
    red[n] = acc * al[n];
    __syncthreads();
    for (int s = 64; s; s >>= 1) { if (n < s) red[n] += red[n + s]; __syncthreads(); }
    if (n == 0) g_sl[b] = red[0];
    __syncthreads();
    red[n] = acc * ar[n];
    __syncthreads();
    for (int s = 64; s; s >>= 1) { if (n < s) red[n] += red[n + s]; __syncthreads(); }
    if (n == 0) g_sr[b] = red[0];
}

// ---------------- graph-level GAT ----------------
__global__ void k_fg(const int* __restrict__ fgs, const int* __restrict__ fgd,
                     const float* __restrict__ b3) {
    int w = (blockIdx.x * blockDim.x + threadIdx.x) >> 5;
    int lane = threadIdx.x & 31;
    if (w >= BB) return;
    float srb = g_sr[w];
    float mx = -3.4e38f;
    for (int i = lane; i < EFE; i += 32) {
        if (fgd[i] == w) {
            float s = g_sl[fgs[i]] + srb;
            s = (s >= 0.f) ? s : 0.2f * s;
            mx = fmaxf(mx, s);
        }
    }
    #pragma unroll
    for (int off = 16; off; off >>= 1)
        mx = fmaxf(mx, __shfl_xor_sync(0xffffffffu, mx, off));
    float sm = 0.f;
    for (int i = lane; i < EFE; i += 32) {
        if (fgd[i] == w) {
            float s = g_sl[fgs[i]] + srb;
            s = (s >= 0.f) ? s : 0.2f * s;
            sm += expf(s - mx);
        }
    }
    #pragma unroll
    for (int off = 16; off; off >>= 1)
        sm += __shfl_xor_sync(0xffffffffu, sm, off);
    float4 acc = make_float4(0.f, 0.f, 0.f, 0.f);
    if (sm > 0.f) {
        float inv = 1.0f / sm;
        for (int i = 0; i < EFE; i++) {
            if (fgd[i] != w) continue;
            float s = g_sl[fgs[i]] + srb;
            s = (s >= 0.f) ? s : 0.2f * s;
            float coef = expf(s - mx) * inv;
            float4 f = ((const float4*)g_ft)[fgs[i] * 32 + lane];
            acc.x += coef * f.x; acc.y += coef * f.y;
            acc.z += coef * f.z; acc.w += coef * f.w;
        }
    }
    float4 bb = ((const float4*)b3)[lane];
    acc.x = fmaxf(acc.x + bb.x, 0.f); acc.y = fmaxf(acc.y + bb.y, 0.f);
    acc.z = fmaxf(acc.z + bb.z, 0.f); acc.w = fmaxf(acc.w + bb.w, 0.f);
    ((float4*)g_gv)[w * 32 + lane] = acc;
}

// ---------------- final ----------------
__global__ void k_final(const float* __restrict__ Wl, const float* __restrict__ bl,
                        const float* __restrict__ Wc, const float* __restrict__ bc,
                        float* __restrict__ out) {
    __shared__ float gs[DD];
    __shared__ float r0[DD], r1[DD];
    int b = blockIdx.x, n = threadIdx.x;
    gs[n] = g_gv[b * DD + n];
    __syncthreads();
    float acc = bl[n];
    #pragma unroll 8
    for (int k = 0; k < DD; k++) acc += gs[k] * Wl[k * DD + n];
    acc = fmaxf(acc, 0.f);
    r0[n] = acc * Wc[n * 2];
    r1[n] = acc * Wc[n * 2 + 1];
    __syncthreads();
    for (int s = 64; s; s >>= 1) {
        if (n < s) { r0[n] += r0[n + s]; r1[n] += r1[n + s]; }
        __syncthreads();
    }
    if (n == 0) {
        out[b * 2] = r0[0] + bc[0];
        out[b * 2 + 1] = r1[0] + bc[1];
    }
}

// ---------------- host ----------------
extern "C" void kernel_launch(void* const* d_in, const int* in_sizes, int n_in,
                              void* d_out, int out_size) {
    const int* tokens_h = (const int*)d_in[0];
    const int* tokens_e = (const int*)d_in[1];
    const int* src = (const int*)d_in[2];
    const int* dst = (const int*)d_in[3];
    const int* fg_src = (const int*)d_in[4];
    const int* fg_dst = (const int*)d_in[5];
    const float* token_emb = (const float*)d_in[6];
    const float* e_token_emb = (const float*)d_in[7];
    const float* W_ni = (const float*)d_in[8];
    const float* W_nj = (const float*)d_in[9];
    const float* W_fij = (const float*)d_in[10];
    const float* W_node = (const float*)d_in[11];
    const float* attn_e = (const float*)d_in[12];
    const float* bias_e = (const float*)d_in[13];
    const float* Wf = (const float*)d_in[14];
    const float* bf = (const float*)d_in[15];
    const float* W3 = (const float*)d_in[16];
    const float* al3 = (const float*)d_in[17];
    const float* ar3 = (const float*)d_in[18];
    const float* b3 = (const float*)d_in[19];
    const float* Wl = (const float*)d_in[20];
    const float* bl = (const float*)d_in[21];
    const float* Wc = (const float*)d_in[22];
    const float* bc = (const float*)d_in[23];
    float* out = (float*)d_out;

    unsigned *eph[2], *hph[2], *hpl[2], *fni16, *fnj16, *hs16;
    float *hfin, *hsort;
    cudaGetSymbolAddress((void**)&eph[0], g_eph0);
    cudaGetSymbolAddress((void**)&eph[1], g_eph1);
    cudaGetSymbolAddress((void**)&hph[0], g_hph0);
    cudaGetSymbolAddress((void**)&hpl[0], g_hpl0);
    cudaGetSymbolAddress((void**)&hph[1], g_hph1);
    cudaGetSymbolAddress((void**)&hpl[1], g_hpl1);
    cudaGetSymbolAddress((void**)&fni16, g_fni16);
    cudaGetSymbolAddress((void**)&fnj16, g_fnj16);
    cudaGetSymbolAddress((void**)&hs16, g_hs16);
    cudaGetSymbolAddress((void**)&hfin, g_hfin);
    cudaGetSymbolAddress((void**)&hsort, g_hsort);

    cudaFuncSetAttribute(k_mm2h, cudaFuncAttributeMaxDynamicSharedMemorySize, SMEM_T1);
    cudaFuncSetAttribute(k_mmhs, cudaFuncAttributeMaxDynamicSharedMemorySize, SMEM_T1);
    cudaFuncSetAttribute(k_mmbr, cudaFuncAttributeMaxDynamicSharedMemorySize, SMEM_T3);
    cudaFuncSetAttribute(k_edge, cudaFuncAttributeMaxDynamicSharedMemorySize, SMEM_T1);
    cudaFuncSetAttribute(k_wpack, cudaFuncAttributeMaxDynamicSharedMemorySize, 129 * 128 * 4);

    // side stream + fork/join events (created once; no device memory involved)
    static cudaStream_t sB = nullptr;
    static cudaEvent_t evF = nullptr, evJ = nullptr, evF2 = nullptr, evJ2 = nullptr;
    if (sB == nullptr) {
        cudaStreamCreateWithFlags(&sB, cudaStreamNonBlocking);
        cudaEventCreateWithFlags(&evF, cudaEventDisableTiming);
        cudaEventCreateWithFlags(&evJ, cudaEventDisableTiming);
        cudaEventCreateWithFlags(&evF2, cudaEventDisableTiming);
        cudaEventCreateWithFlags(&evJ2, cudaEventDisableTiming);
    }
    cudaStream_t s0 = (cudaStream_t)0;

    // fork: CSR build + edge permutation on sB (independent of h-path setup)
    cudaEventRecord(evF, s0);
    cudaStreamWaitEvent(sB, evF, 0);
    k_zero_cursor<<<(NN + 255) / 256, 256, 0, sB>>>();
    k_count<<<(EE + 255) / 256, 256, 0, sB>>>(dst);
    k_scan<<<1, 1024, 0, sB>>>();
    k_copy_cursor<<<(NN + 255) / 256, 256, 0, sB>>>();
    k_scatter<<<(EE + 255) / 256, 256, 0, sB>>>(dst);
    k_permute<<<(EE + 255) / 256, 256, 0, sB>>>(src, dst, tokens_e);
    cudaEventRecord(evJ, sB);

    // main stream: h-path setup + layer-0 fni/fnj GEMM
    k_hinit<<<(NN * 32 + 255) / 256, 256>>>(tokens_h, token_emb);
    k_embw<<<100, 128>>>(e_token_emb, W_fij);
    k_wpack<<<33, 256, 129 * 128 * 4>>>(W_ni, W_nj, W_node, W_fij, Wf);

    dim3 g2(NN / 128, 2, 1);
    k_mm2h<<<g2, 256, SMEM_T1>>>(hph[0], 0, fni16, fnj16);

    // layer-0 hs GEMM on side stream (after h-path setup), overlapping k_edge_l0
    cudaEventRecord(evF2, s0);
    cudaStreamWaitEvent(sB, evF2, 0);
    k_mmhs<<<NN / 128, 256, SMEM_T1, sB>>>(hph[0], 0, hs16);
    cudaEventRecord(evJ2, sB);

    // join: layer-0 edge kernel needs the permuted edge arrays
    cudaStreamWaitEvent(s0, evJ, 0);
    k_edge_l0<<<(EE * 32 + 255) / 256, 256>>>(bias_e, attn_e, eph[1], fni16, fnj16);
    // join: agg needs hs
    cudaStreamWaitEvent(s0, evJ2, 0);
    k_agg<<<(NN * 32 + 255) / 256, 256>>>(hs16, hph[1], hpl[1]);

    for (int l = 1; l < LL; l++) {
        const float* bias_l = bias_e + l * DD;
        const float* attn_l = attn_e + l * DD;
        int hi = l & 1, ho = (l + 1) & 1;
        int writef = (l < LL - 1) ? 1 : 0;

        // fork after k_agg(l-1): hs GEMM overlaps with fni/fnj GEMM + edge kernel
        cudaEventRecord(evF, s0);
        cudaStreamWaitEvent(sB, evF, 0);
        k_mmhs<<<NN / 128, 256, SMEM_T1, sB>>>(hph[hi], l, hs16);
        cudaEventRecord(evJ, sB);

        k_mm2h<<<g2, 256, SMEM_T1>>>(hph[hi], l, fni16, fnj16);
        k_edge<<<EE / 128, 256, SMEM_T1>>>(eph[hi], l, bias_l, attn_l,
                                           eph[ho], fni16, fnj16, writef);

        // join before aggregation (needs hs)
        cudaStreamWaitEvent(s0, evJ, 0);
        k_agg<<<(NN * 32 + 255) / 256, 256>>>(hs16, hph[ho], hpl[ho]);
    }

    k_mmbr<<<NN / 128, 256, SMEM_T3>>>(hph[0], hpl[0], hfin, bf);
    k_sort<<<(NN * 32 + 255) / 256, 256>>>(hfin, hsort);
    k_topk<<<BB / 4, 128>>>();
    k_ft<<<BB, 128>>>(W3, al3, ar3, hsort);
    k_fg<<<(BB * 32 + 255) / 256, 256>>>(fg_src, fg_dst, b3);
    k_final<<<BB, 128>>>(Wl, bl, Wc, bc, out);
}